// round 6
// baseline (speedup 1.0000x reference)
#include <cuda_runtime.h>
#include <math.h>

#define BATCH 1024
#define SEQ   250
#define EMB   100
#define UNITS 128
#define GATES 512   // 4*UNITS, gate order i,f,g,o
#define DENSE 32

// Scratch: xz = emb[tokens] @ Wx + b, layout [t][b][512] (524 MB)
__device__ float g_xz[(size_t)SEQ * BATCH * GATES];

// ---- packed f32x2 helpers (sm_100a) --------------------------------------
__device__ __forceinline__ unsigned long long pack2(float a, float b) {
    unsigned long long r;
    asm("mov.b64 %0, {%1, %2};" : "=l"(r) : "f"(a), "f"(b));
    return r;
}
__device__ __forceinline__ void unpack2(unsigned long long v, float& a, float& b) {
    asm("mov.b64 {%0, %1}, %2;" : "=f"(a), "=f"(b) : "l"(v));
}
__device__ __forceinline__ void fma2(unsigned long long& d, unsigned long long a,
                                     unsigned long long b) {
    asm("fma.rn.f32x2 %0, %1, %2, %0;" : "+l"(d) : "l"(a), "l"(b));
}
__device__ __forceinline__ void add2(unsigned long long& d, unsigned long long a) {
    asm("add.rn.f32x2 %0, %0, %1;" : "+l"(d) : "l"(a));
}

// ---------------------------------------------------------------------------
// K1: embedding gather + input projection GEMM (unchanged — passing at ~670us)
// ---------------------------------------------------------------------------
#define K1_ROWS 64
#define K1_COLS 128
#define K1_KC   25

__global__ __launch_bounds__(256) void k1_embed_proj(
    const int* __restrict__ tokens, const float* __restrict__ emb,
    const float* __restrict__ Wx, const float* __restrict__ bias)
{
    __shared__ float As[K1_KC * K1_ROWS];     // transposed: As[e][row]
    __shared__ float Bs[K1_KC * K1_COLS];     // Bs[e][col]
    __shared__ int   tk[K1_ROWS];

    const int tid  = threadIdx.x;
    const int row0 = blockIdx.x * K1_ROWS;
    const int c0   = blockIdx.y * K1_COLS;

    if (tid < K1_ROWS) tk[tid] = tokens[row0 + tid];

    const int rg = tid >> 5;
    const int cg = tid & 31;

    unsigned long long acc2[4][4];
    {
        const float4 bv = *(const float4*)&bias[c0 + cg * 4];
        #pragma unroll
        for (int rp = 0; rp < 4; rp++) {
            acc2[rp][0] = pack2(bv.x, bv.x);
            acc2[rp][1] = pack2(bv.y, bv.y);
            acc2[rp][2] = pack2(bv.z, bv.z);
            acc2[rp][3] = pack2(bv.w, bv.w);
        }
    }
    __syncthreads();

    for (int kc = 0; kc < EMB; kc += K1_KC) {
        for (int idx = tid; idx < K1_KC * K1_ROWS; idx += 256) {
            int e = idx >> 6, r = idx & 63;
            As[idx] = emb[(size_t)tk[r] * EMB + kc + e];
        }
        for (int idx = tid; idx < K1_KC * K1_COLS; idx += 256) {
            int e = idx >> 7, j = idx & 127;
            Bs[idx] = Wx[(kc + e) * GATES + c0 + j];
        }
        __syncthreads();

        #pragma unroll
        for (int k = 0; k < K1_KC; k++) {
            const ulonglong2* ap = (const ulonglong2*)&As[k * K1_ROWS + rg * 8];
            ulonglong2 a01 = ap[0];
            ulonglong2 a23 = ap[1];
            unsigned long long arp[4] = {a01.x, a01.y, a23.x, a23.y};

            float4 b4 = *(const float4*)&Bs[k * K1_COLS + cg * 4];
            unsigned long long bs[4] = {pack2(b4.x, b4.x), pack2(b4.y, b4.y),
                                        pack2(b4.z, b4.z), pack2(b4.w, b4.w)};
            #pragma unroll
            for (int rp = 0; rp < 4; rp++) {
                fma2(acc2[rp][0], arp[rp], bs[0]);
                fma2(acc2[rp][1], arp[rp], bs[1]);
                fma2(acc2[rp][2], arp[rp], bs[2]);
                fma2(acc2[rp][3], arp[rp], bs[3]);
            }
        }
        __syncthreads();
    }

    #pragma unroll
    for (int rp = 0; rp < 4; rp++) {
        float lo[4], hi[4];
        #pragma unroll
        for (int j = 0; j < 4; j++) unpack2(acc2[rp][j], lo[j], hi[j]);
        #pragma unroll
        for (int h = 0; h < 2; h++) {
            int gr = row0 + rg * 8 + rp * 2 + h;
            int b  = gr / SEQ;
            int t  = gr - b * SEQ;
            size_t off = ((size_t)t * BATCH + b) * GATES + c0 + cg * 4;
            float4 v = h ? make_float4(hi[0], hi[1], hi[2], hi[3])
                         : make_float4(lo[0], lo[1], lo[2], lo[3]);
            __stcs((float4*)&g_xz[off], v);
        }
    }
}

// ---------------------------------------------------------------------------
// K2: LSTM recurrence + dense head (v3)
//   128 CTAs x 8 batch rows, 512 threads = 16 warps.
//   Thread (u = tid&127, kh = tid>>7 in 0..3) accumulates z over 32 k's
//   [kh*32, kh*32+32) for unit u, 4 gates, all 8 rows (f32x2 row pairs).
//   4-way partial exchange via smem; thread (u,kh) finalizes row-pair kh
//   (rows 2kh, 2kh+1) — so xz is seeded AFTER reduction, only for owned rows,
//   with coalesced prefetched loads.
//   Wh: 80 k's (20/quarter) staged in smem as [slot][u][4 gates] (one LDS.128
//   per k); 12 residual k's per quarter stream from L2 (12MB/step chip-wide,
//   well under the LTS cap).
// ---------------------------------------------------------------------------
#define K2_THREADS   512
#define K2_KQ        32   // k's per quarter
#define K2_SMEM_KQ   20   // smem-resident k's per quarter
#define K2_WHS_BYTES (4 * K2_SMEM_KQ * UNITS * 4 * 4)        // 163840
#define K2_HBUF_OFF  K2_WHS_BYTES
#define K2_PART_OFF  (K2_HBUF_OFF + 2 * UNITS * 8 * 4)       // +8192  = 172032
#define K2_D1S_OFF   (K2_PART_OFF + 4 * 3 * UNITS * 4 * 8)   // +49152 = 221184
#define K2_SMEM_TOT  (K2_D1S_OFF + 8 * DENSE * 4)            // 222208

__device__ __forceinline__ float fast_sigmoid(float x) {
    return 1.0f / (1.0f + __expf(-x));
}
__device__ __forceinline__ float fast_tanh(float x) {
    x = fminf(fmaxf(x, -15.0f), 15.0f);
    float e = __expf(2.0f * x);
    return (e - 1.0f) / (e + 1.0f);
}

__global__ __launch_bounds__(K2_THREADS, 1) void k2_lstm_head(
    const float* __restrict__ Wh,
    const float* __restrict__ W1, const float* __restrict__ b1,
    const float* __restrict__ W2, const float* __restrict__ b2,
    float* __restrict__ out)
{
    extern __shared__ unsigned char smem_raw[];
    float* whs = (float*)smem_raw;                                   // [80][128][4]
    float (*hbuf)[UNITS][8] = (float (*)[UNITS][8])(smem_raw + K2_HBUF_OFF);
    unsigned long long* part =
        (unsigned long long*)(smem_raw + K2_PART_OFF);  // [dest4][src3][u128][g4]
    float (*d1s)[DENSE] = (float (*)[DENSE])(smem_raw + K2_D1S_OFF);

    const int tid = threadIdx.x;
    const int u   = tid & 127;
    const int kh  = tid >> 7;          // 0..3, warp-uniform
    const int b0  = blockIdx.x * 8;

    // Stage Wh into smem: slot s = kq*20 + j -> k = kq*32 + j,
    // whs[s][u][g] = Wh[k][g*128+u]  (coalesced per (s,g))
    for (int idx = tid; idx < 4 * K2_SMEM_KQ * UNITS; idx += K2_THREADS) {
        int s  = idx >> 7;
        int uu = idx & 127;
        int k  = (s / K2_SMEM_KQ) * K2_KQ + (s % K2_SMEM_KQ);
        float4 w;
        w.x = Wh[(size_t)k * GATES + 0 * UNITS + uu];
        w.y = Wh[(size_t)k * GATES + 1 * UNITS + uu];
        w.z = Wh[(size_t)k * GATES + 2 * UNITS + uu];
        w.w = Wh[(size_t)k * GATES + 3 * UNITS + uu];
        *(float4*)&whs[(size_t)idx * 4] = w;
    }

    // zero h
    for (int i = tid; i < 2 * UNITS * 8; i += K2_THREADS)
        (&hbuf[0][0][0])[i] = 0.0f;
    float c[2] = {0.0f, 0.0f};          // cell state for rows 2kh, 2kh+1
    __syncthreads();

    const int k0 = kh * K2_KQ;
    const float4* wts = (const float4*)whs + (size_t)kh * K2_SMEM_KQ * UNITS + u;
    const float*  wg  = Wh + (size_t)(k0 + K2_SMEM_KQ) * GATES + u;

    int cur = 0;
    for (int t = 0; t < SEQ; t++) {
        // Prefetch xz for OWNED rows only (2kh, 2kh+1), coalesced in u.
        float xzv[2][4];
        {
            const float* xzb =
                &g_xz[((size_t)t * BATCH + b0 + 2 * kh) * GATES + u];
            #pragma unroll
            for (int g = 0; g < 4; g++) {
                xzv[0][g] = __ldcs(xzb + g * UNITS);
                xzv[1][g] = __ldcs(xzb + GATES + g * UNITS);
            }
        }

        unsigned long long z[4][4];
        #pragma unroll
        for (int rp = 0; rp < 4; rp++)
            #pragma unroll
            for (int g = 0; g < 4; g++) z[rp][g] = 0ull;

        const float (*hb)[8] = hbuf[cur];

        // smem-resident k's
        #pragma unroll 5
        for (int kk = 0; kk < K2_SMEM_KQ; kk++) {
            const ulonglong2* hp2 = (const ulonglong2*)&hb[k0 + kk][0];
            ulonglong2 hA = hp2[0], hB = hp2[1];
            unsigned long long hp[4] = {hA.x, hA.y, hB.x, hB.y};

            float4 w4 = wts[(size_t)kk * UNITS];
            unsigned long long wp[4] = {pack2(w4.x, w4.x), pack2(w4.y, w4.y),
                                        pack2(w4.z, w4.z), pack2(w4.w, w4.w)};
            #pragma unroll
            for (int g = 0; g < 4; g++) {
                fma2(z[0][g], hp[0], wp[g]);
                fma2(z[1][g], hp[1], wp[g]);
                fma2(z[2][g], hp[2], wp[g]);
                fma2(z[3][g], hp[3], wp[g]);
            }
        }
        // residual k's from global (L2)
        #pragma unroll 4
        for (int kk = K2_SMEM_KQ; kk < K2_KQ; kk++) {
            const ulonglong2* hp2 = (const ulonglong2*)&hb[k0 + kk][0];
            ulonglong2 hA = hp2[0], hB = hp2[1];
            unsigned long long hp[4] = {hA.x, hA.y, hB.x, hB.y};

            const float* wk = wg + (size_t)(kk - K2_SMEM_KQ) * GATES;
            #pragma unroll
            for (int g = 0; g < 4; g++) {
                float w = __ldg(wk + g * UNITS);
                unsigned long long wp = pack2(w, w);
                fma2(z[0][g], hp[0], wp);
                fma2(z[1][g], hp[1], wp);
                fma2(z[2][g], hp[2], wp);
                fma2(z[3][g], hp[3], wp);
            }
        }

        // Exchange: write the 3 non-owned row-pair partials to their owners.
        #pragma unroll
        for (int d = 0; d < 4; d++) {
            if (d == kh) continue;
            int slot = ((kh - d + 4) & 3) - 1;          // 0..2
            ulonglong2* ps =
                (ulonglong2*)&part[(((size_t)d * 3 + slot) * UNITS + u) * 4];
            ps[0] = make_ulonglong2(z[d][0], z[d][1]);
            ps[1] = make_ulonglong2(z[d][2], z[d][3]);
        }
        __syncthreads();
        // Reduce owned row-pair kh
        #pragma unroll
        for (int slot = 0; slot < 3; slot++) {
            const ulonglong2* pm =
                (const ulonglong2*)&part[(((size_t)kh * 3 + slot) * UNITS + u) * 4];
            ulonglong2 p0 = pm[0], p1 = pm[1];
            add2(z[kh][0], p0.x); add2(z[kh][1], p0.y);
            add2(z[kh][2], p1.x); add2(z[kh][3], p1.y);
        }

        // gate math for rows 2kh, 2kh+1
        const int nxt = cur ^ 1;
        float hv[2];
        {
            float zi[2][4];
            #pragma unroll
            for (int g = 0; g < 4; g++) unpack2(z[kh][g], zi[0][g], zi[1][g]);
            #pragma unroll
            for (int h = 0; h < 2; h++) {
                float ig = fast_sigmoid(zi[h][0] + xzv[h][0]);
                float fg = fast_sigmoid(zi[h][1] + xzv[h][1]);
                float gg = fast_tanh   (zi[h][2] + xzv[h][2]);
                float og = fast_sigmoid(zi[h][3] + xzv[h][3]);
                float cc = fg * c[h] + ig * gg;
                c[h] = cc;
                hv[h] = og * fast_tanh(cc);
            }
        }
        *(float2*)&hbuf[nxt][u][2 * kh] = make_float2(hv[0], hv[1]);
        __syncthreads();
        cur = nxt;
    }

    // ---- dense head: relu(h @ W1 + b1) @ W2 + b2, softmax ----
    if (tid < 256) {
        int r = tid >> 5;            // 0..7
        int j = tid & 31;            // 0..31
        float a = b1[j];
        #pragma unroll 8
        for (int k = 0; k < UNITS; k++) a += hbuf[cur][k][r] * W1[k * DENSE + j];
        d1s[r][j] = fmaxf(a, 0.0f);
    }
    __syncthreads();
    if (tid < 8) {
        float l0 = b2[0], l1 = b2[1];
        #pragma unroll
        for (int j = 0; j < DENSE; j++) {
            float d = d1s[tid][j];
            l0 += d * W2[j * 2 + 0];
            l1 += d * W2[j * 2 + 1];
        }
        float m  = fmaxf(l0, l1);
        float e0 = __expf(l0 - m), e1 = __expf(l1 - m);
        float s  = 1.0f / (e0 + e1);
        out[(b0 + tid) * 2 + 0] = e0 * s;
        out[(b0 + tid) * 2 + 1] = e1 * s;
    }
}

// ---------------------------------------------------------------------------
extern "C" void kernel_launch(void* const* d_in, const int* in_sizes, int n_in,
                              void* d_out, int out_size)
{
    const int*   tokens = (const int*)  d_in[0];
    const float* emb    = (const float*)d_in[1];
    const float* Wx     = (const float*)d_in[2];
    const float* Wh     = (const float*)d_in[3];
    const float* lb     = (const float*)d_in[4];
    const float* W1     = (const float*)d_in[5];
    const float* b1     = (const float*)d_in[6];
    const float* W2     = (const float*)d_in[7];
    const float* b2     = (const float*)d_in[8];
    float* out = (float*)d_out;

    cudaFuncSetAttribute(k2_lstm_head,
                         cudaFuncAttributeMaxDynamicSharedMemorySize, K2_SMEM_TOT);

    dim3 g1(BATCH * SEQ / K1_ROWS, GATES / K1_COLS);   // (4000, 4)
    k1_embed_proj<<<g1, 256>>>(tokens, emb, Wx, lb);
    k2_lstm_head<<<BATCH / 8, K2_THREADS, K2_SMEM_TOT>>>(Wh, W1, b1, W2, b2, out);
}

// round 8
// speedup vs baseline: 1.1590x; 1.1590x over previous
#include <cuda_runtime.h>
#include <math.h>

#define BATCH 1024
#define SEQ   250
#define EMB   100
#define UNITS 128
#define GATES 512   // 4*UNITS, gate order i,f,g,o
#define DENSE 32

// Scratch: xz = emb[tokens] @ Wx + b, layout [t][b][512] (524 MB)
__device__ float g_xz[(size_t)SEQ * BATCH * GATES];

// ---- packed f32x2 helpers (sm_100a) --------------------------------------
__device__ __forceinline__ unsigned long long pack2(float a, float b) {
    unsigned long long r;
    asm("mov.b64 %0, {%1, %2};" : "=l"(r) : "f"(a), "f"(b));
    return r;
}
__device__ __forceinline__ void unpack2(unsigned long long v, float& a, float& b) {
    asm("mov.b64 {%0, %1}, %2;" : "=f"(a), "=f"(b) : "l"(v));
}
__device__ __forceinline__ void fma2(unsigned long long& d, unsigned long long a,
                                     unsigned long long b) {
    asm("fma.rn.f32x2 %0, %1, %2, %0;" : "+l"(d) : "l"(a), "l"(b));
}
__device__ __forceinline__ void add2(unsigned long long& d, unsigned long long a) {
    asm("add.rn.f32x2 %0, %0, %1;" : "+l"(d) : "l"(a));
}

// ---------------------------------------------------------------------------
// K1: embedding gather + input projection GEMM (unchanged)
// ---------------------------------------------------------------------------
#define K1_ROWS 64
#define K1_COLS 128
#define K1_KC   25

__global__ __launch_bounds__(256) void k1_embed_proj(
    const int* __restrict__ tokens, const float* __restrict__ emb,
    const float* __restrict__ Wx, const float* __restrict__ bias)
{
    __shared__ float As[K1_KC * K1_ROWS];     // transposed: As[e][row]
    __shared__ float Bs[K1_KC * K1_COLS];     // Bs[e][col]
    __shared__ int   tk[K1_ROWS];

    const int tid  = threadIdx.x;
    const int row0 = blockIdx.x * K1_ROWS;
    const int c0   = blockIdx.y * K1_COLS;

    if (tid < K1_ROWS) tk[tid] = tokens[row0 + tid];

    const int rg = tid >> 5;
    const int cg = tid & 31;

    unsigned long long acc2[4][4];
    {
        const float4 bv = *(const float4*)&bias[c0 + cg * 4];
        #pragma unroll
        for (int rp = 0; rp < 4; rp++) {
            acc2[rp][0] = pack2(bv.x, bv.x);
            acc2[rp][1] = pack2(bv.y, bv.y);
            acc2[rp][2] = pack2(bv.z, bv.z);
            acc2[rp][3] = pack2(bv.w, bv.w);
        }
    }
    __syncthreads();

    for (int kc = 0; kc < EMB; kc += K1_KC) {
        for (int idx = tid; idx < K1_KC * K1_ROWS; idx += 256) {
            int e = idx >> 6, r = idx & 63;
            As[idx] = emb[(size_t)tk[r] * EMB + kc + e];
        }
        for (int idx = tid; idx < K1_KC * K1_COLS; idx += 256) {
            int e = idx >> 7, j = idx & 127;
            Bs[idx] = Wx[(kc + e) * GATES + c0 + j];
        }
        __syncthreads();

        #pragma unroll
        for (int k = 0; k < K1_KC; k++) {
            const ulonglong2* ap = (const ulonglong2*)&As[k * K1_ROWS + rg * 8];
            ulonglong2 a01 = ap[0];
            ulonglong2 a23 = ap[1];
            unsigned long long arp[4] = {a01.x, a01.y, a23.x, a23.y};

            float4 b4 = *(const float4*)&Bs[k * K1_COLS + cg * 4];
            unsigned long long bs[4] = {pack2(b4.x, b4.x), pack2(b4.y, b4.y),
                                        pack2(b4.z, b4.z), pack2(b4.w, b4.w)};
            #pragma unroll
            for (int rp = 0; rp < 4; rp++) {
                fma2(acc2[rp][0], arp[rp], bs[0]);
                fma2(acc2[rp][1], arp[rp], bs[1]);
                fma2(acc2[rp][2], arp[rp], bs[2]);
                fma2(acc2[rp][3], arp[rp], bs[3]);
            }
        }
        __syncthreads();
    }

    #pragma unroll
    for (int rp = 0; rp < 4; rp++) {
        float lo[4], hi[4];
        #pragma unroll
        for (int j = 0; j < 4; j++) unpack2(acc2[rp][j], lo[j], hi[j]);
        #pragma unroll
        for (int h = 0; h < 2; h++) {
            int gr = row0 + rg * 8 + rp * 2 + h;
            int b  = gr / SEQ;
            int t  = gr - b * SEQ;
            size_t off = ((size_t)t * BATCH + b) * GATES + c0 + cg * 4;
            float4 v = h ? make_float4(hi[0], hi[1], hi[2], hi[3])
                         : make_float4(lo[0], lo[1], lo[2], lo[3]);
            __stcs((float4*)&g_xz[off], v);
        }
    }
}

// ---------------------------------------------------------------------------
// K2: LSTM recurrence + dense head (v4)
//   128 CTAs x 8 batch rows, 256 threads = 8 warps, 2-way k-split.
//   Thread (u = tid&127, kh = tid>>7) accumulates z over 64 k's for unit u,
//   4 gates, all 8 rows (f32x2 row pairs):
//     - k in [kh*64, kh*64+48):   Wh from smem, one LDS.128 per k
//     - k in [kh*64+48, kh*64+64): Wh REGISTER-RESIDENT (loaded once, 64 regs)
//   => ZERO global loads in the recurrence except the coalesced xz prefetch
//   for the thread's own 4 rows. 2-way partial exchange via padded smem;
//   thread (u,kh) finalizes rows 4kh..4kh+3.
// ---------------------------------------------------------------------------
#define K2_THREADS   256
#define K2_KH        64   // k's per half
#define K2_SMEM_KH   48   // smem-resident k's per half
#define K2_REG_KH    16   // register-resident k's per half
#define K2_WHS_BYTES (2 * K2_SMEM_KH * UNITS * 4 * 4)        // 196608
#define K2_HBUF_OFF  K2_WHS_BYTES
#define K2_PART_OFF  (K2_HBUF_OFF + 2 * UNITS * 8 * 4)       // +8192  = 204800
#define K2_D1S_OFF   (K2_PART_OFF + 2 * UNITS * 10 * 8)      // +20480 = 225280
#define K2_SMEM_TOT  (K2_D1S_OFF + 8 * DENSE * 4)            // 226304

__device__ __forceinline__ float fast_sigmoid(float x) {
    return 1.0f / (1.0f + __expf(-x));
}
__device__ __forceinline__ float fast_tanh(float x) {
    x = fminf(fmaxf(x, -15.0f), 15.0f);
    float e = __expf(2.0f * x);
    return (e - 1.0f) / (e + 1.0f);
}

__global__ __launch_bounds__(K2_THREADS, 1) void k2_lstm_head(
    const float* __restrict__ Wh,
    const float* __restrict__ W1, const float* __restrict__ b1,
    const float* __restrict__ W2, const float* __restrict__ b2,
    float* __restrict__ out)
{
    extern __shared__ unsigned char smem_raw[];
    float* whs = (float*)smem_raw;                                   // [96][128][4]
    float (*hbuf)[UNITS][8] = (float (*)[UNITS][8])(smem_raw + K2_HBUF_OFF);
    unsigned long long* part =
        (unsigned long long*)(smem_raw + K2_PART_OFF);   // [dest2][u128][10] 80B rows
    float (*d1s)[DENSE] = (float (*)[DENSE])(smem_raw + K2_D1S_OFF);

    const int tid = threadIdx.x;
    const int u   = tid & 127;
    const int kh  = tid >> 7;          // 0 or 1, warp-uniform
    const int b0  = blockIdx.x * 8;

    // Stage smem Wh: slot s = half*48 + j -> k = half*64 + j,
    // whs[s][u][g] = Wh[k][g*128+u]  (coalesced in uu for each (s,g))
    for (int idx = tid; idx < 2 * K2_SMEM_KH * UNITS; idx += K2_THREADS) {
        int s  = idx >> 7;
        int uu = idx & 127;
        int k  = (s / K2_SMEM_KH) * K2_KH + (s % K2_SMEM_KH);
        float4 w;
        w.x = Wh[(size_t)k * GATES + 0 * UNITS + uu];
        w.y = Wh[(size_t)k * GATES + 1 * UNITS + uu];
        w.z = Wh[(size_t)k * GATES + 2 * UNITS + uu];
        w.w = Wh[(size_t)k * GATES + 3 * UNITS + uu];
        *(float4*)&whs[(size_t)idx * 4] = w;
    }

    // Register-resident residual weights: k = kh*64 + 48 + j  (loaded ONCE)
    float wreg[K2_REG_KH][4];
    {
        const float* wbase = Wh + (size_t)(kh * K2_KH + K2_SMEM_KH) * GATES + u;
        #pragma unroll
        for (int j = 0; j < K2_REG_KH; j++)
            #pragma unroll
            for (int g = 0; g < 4; g++)
                wreg[j][g] = __ldg(wbase + (size_t)j * GATES + g * UNITS);
    }

    // zero h
    for (int i = tid; i < 2 * UNITS * 8; i += K2_THREADS)
        (&hbuf[0][0][0])[i] = 0.0f;
    float c[4] = {0.0f, 0.0f, 0.0f, 0.0f};   // cell state, rows 4kh..4kh+3
    __syncthreads();

    const int k0 = kh * K2_KH;
    const float4* wts = (const float4*)whs + (size_t)kh * K2_SMEM_KH * UNITS + u;

    int cur = 0;
    for (int t = 0; t < SEQ; t++) {
        // Prefetch xz for OWNED rows (4kh..4kh+3), coalesced in u.
        float xzv[4][4];
        {
            const float* xzb =
                &g_xz[((size_t)t * BATCH + b0 + 4 * kh) * GATES + u];
            #pragma unroll
            for (int r = 0; r < 4; r++)
                #pragma unroll
                for (int g = 0; g < 4; g++)
                    xzv[r][g] = __ldcs(xzb + (size_t)r * GATES + g * UNITS);
        }

        unsigned long long z[4][4];
        #pragma unroll
        for (int rp = 0; rp < 4; rp++)
            #pragma unroll
            for (int g = 0; g < 4; g++) z[rp][g] = 0ull;

        const float (*hb)[8] = hbuf[cur];

        // smem-resident k's (w: one LDS.128; h: broadcast 2x LDS.128)
        #pragma unroll 8
        for (int kk = 0; kk < K2_SMEM_KH; kk++) {
            const ulonglong2* hp2 = (const ulonglong2*)&hb[k0 + kk][0];
            ulonglong2 hA = hp2[0], hB = hp2[1];
            unsigned long long hp[4] = {hA.x, hA.y, hB.x, hB.y};

            float4 w4 = wts[(size_t)kk * UNITS];
            unsigned long long wp[4] = {pack2(w4.x, w4.x), pack2(w4.y, w4.y),
                                        pack2(w4.z, w4.z), pack2(w4.w, w4.w)};
            #pragma unroll
            for (int g = 0; g < 4; g++) {
                fma2(z[0][g], hp[0], wp[g]);
                fma2(z[1][g], hp[1], wp[g]);
                fma2(z[2][g], hp[2], wp[g]);
                fma2(z[3][g], hp[3], wp[g]);
            }
        }
        // register-resident k's (no loads except h broadcast)
        #pragma unroll
        for (int j = 0; j < K2_REG_KH; j++) {
            const ulonglong2* hp2 =
                (const ulonglong2*)&hb[k0 + K2_SMEM_KH + j][0];
            ulonglong2 hA = hp2[0], hB = hp2[1];
            unsigned long long hp[4] = {hA.x, hA.y, hB.x, hB.y};
            #pragma unroll
            for (int g = 0; g < 4; g++) {
                unsigned long long wp = pack2(wreg[j][g], wreg[j][g]);
                fma2(z[0][g], hp[0], wp);
                fma2(z[1][g], hp[1], wp);
                fma2(z[2][g], hp[2], wp);
                fma2(z[3][g], hp[3], wp);
            }
        }

        // Ship the two non-owned row-pair partials to the other half.
        {
            const int nrp = (1 - kh) * 2;
            ulonglong2* ps = (ulonglong2*)&part[((size_t)(1 - kh) * UNITS + u) * 10];
            ps[0] = make_ulonglong2(z[nrp][0],     z[nrp][1]);
            ps[1] = make_ulonglong2(z[nrp][2],     z[nrp][3]);
            ps[2] = make_ulonglong2(z[nrp + 1][0], z[nrp + 1][1]);
            ps[3] = make_ulonglong2(z[nrp + 1][2], z[nrp + 1][3]);
        }
        __syncthreads();
        // Reduce owned row-pairs (2kh, 2kh+1)
        const int orp = kh * 2;
        {
            const ulonglong2* pm =
                (const ulonglong2*)&part[((size_t)kh * UNITS + u) * 10];
            ulonglong2 p0 = pm[0], p1 = pm[1], p2 = pm[2], p3 = pm[3];
            add2(z[orp][0], p0.x);     add2(z[orp][1], p0.y);
            add2(z[orp][2], p1.x);     add2(z[orp][3], p1.y);
            add2(z[orp + 1][0], p2.x); add2(z[orp + 1][1], p2.y);
            add2(z[orp + 1][2], p3.x); add2(z[orp + 1][3], p3.y);
        }

        // gate math for rows 4kh..4kh+3
        const int nxt = cur ^ 1;
        float hv[4];
        #pragma unroll
        for (int rr = 0; rr < 2; rr++) {
            float zi[2][4];
            #pragma unroll
            for (int g = 0; g < 4; g++) unpack2(z[orp + rr][g], zi[0][g], zi[1][g]);
            #pragma unroll
            for (int h = 0; h < 2; h++) {
                int j = rr * 2 + h;        // local row 0..3
                float ig = fast_sigmoid(zi[h][0] + xzv[j][0]);
                float fg = fast_sigmoid(zi[h][1] + xzv[j][1]);
                float gg = fast_tanh   (zi[h][2] + xzv[j][2]);
                float og = fast_sigmoid(zi[h][3] + xzv[j][3]);
                float cc = fg * c[j] + ig * gg;
                c[j] = cc;
                hv[j] = og * fast_tanh(cc);
            }
        }
        *(float4*)&hbuf[nxt][u][4 * kh] = make_float4(hv[0], hv[1], hv[2], hv[3]);
        __syncthreads();
        cur = nxt;
    }

    // ---- dense head: relu(h @ W1 + b1) @ W2 + b2, softmax ----
    {
        int r = tid >> 5;            // 0..7
        int j = tid & 31;            // 0..31
        float a = b1[j];
        #pragma unroll 8
        for (int k = 0; k < UNITS; k++) a += hbuf[cur][k][r] * W1[k * DENSE + j];
        d1s[r][j] = fmaxf(a, 0.0f);
    }
    __syncthreads();
    if (tid < 8) {
        float l0 = b2[0], l1 = b2[1];
        #pragma unroll
        for (int j = 0; j < DENSE; j++) {
            float d = d1s[tid][j];
            l0 += d * W2[j * 2 + 0];
            l1 += d * W2[j * 2 + 1];
        }
        float m  = fmaxf(l0, l1);
        float e0 = __expf(l0 - m), e1 = __expf(l1 - m);
        float s  = 1.0f / (e0 + e1);
        out[(b0 + tid) * 2 + 0] = e0 * s;
        out[(b0 + tid) * 2 + 1] = e1 * s;
    }
}

// ---------------------------------------------------------------------------
extern "C" void kernel_launch(void* const* d_in, const int* in_sizes, int n_in,
                              void* d_out, int out_size)
{
    const int*   tokens = (const int*)  d_in[0];
    const float* emb    = (const float*)d_in[1];
    const float* Wx     = (const float*)d_in[2];
    const float* Wh     = (const float*)d_in[3];
    const float* lb     = (const float*)d_in[4];
    const float* W1     = (const float*)d_in[5];
    const float* b1     = (const float*)d_in[6];
    const float* W2     = (const float*)d_in[7];
    const float* b2     = (const float*)d_in[8];
    float* out = (float*)d_out;

    cudaFuncSetAttribute(k2_lstm_head,
                         cudaFuncAttributeMaxDynamicSharedMemorySize, K2_SMEM_TOT);

    dim3 g1(BATCH * SEQ / K1_ROWS, GATES / K1_COLS);   // (4000, 4)
    k1_embed_proj<<<g1, 256>>>(tokens, emb, Wx, lb);
    k2_lstm_head<<<BATCH / 8, K2_THREADS, K2_SMEM_TOT>>>(Wh, W1, b1, W2, b2, out);
}

// round 10
// speedup vs baseline: 1.2440x; 1.0734x over previous
#include <cuda_runtime.h>
#include <math.h>

#define BATCH 1024
#define SEQ   250
#define EMB   100
#define UNITS 128
#define GATES 512   // 4*UNITS, gate order i,f,g,o
#define DENSE 32

// Scratch: xz = emb[tokens] @ Wx + b, layout [t][b][512] (524 MB)
__device__ float g_xz[(size_t)SEQ * BATCH * GATES];

// ---- packed f32x2 helpers (sm_100a) --------------------------------------
__device__ __forceinline__ unsigned long long pack2(float a, float b) {
    unsigned long long r;
    asm("mov.b64 %0, {%1, %2};" : "=l"(r) : "f"(a), "f"(b));
    return r;
}
__device__ __forceinline__ void unpack2(unsigned long long v, float& a, float& b) {
    asm("mov.b64 {%0, %1}, %2;" : "=f"(a), "=f"(b) : "l"(v));
}
__device__ __forceinline__ void fma2(unsigned long long& d, unsigned long long a,
                                     unsigned long long b) {
    asm("fma.rn.f32x2 %0, %1, %2, %0;" : "+l"(d) : "l"(a), "l"(b));
}
__device__ __forceinline__ void add2(unsigned long long& d, unsigned long long a) {
    asm("add.rn.f32x2 %0, %0, %1;" : "+l"(d) : "l"(a));
}

// ---------------------------------------------------------------------------
// K1: embedding gather + input projection GEMM (unchanged)
// ---------------------------------------------------------------------------
#define K1_ROWS 64
#define K1_COLS 128
#define K1_KC   25

__global__ __launch_bounds__(256) void k1_embed_proj(
    const int* __restrict__ tokens, const float* __restrict__ emb,
    const float* __restrict__ Wx, const float* __restrict__ bias)
{
    __shared__ float As[K1_KC * K1_ROWS];     // transposed: As[e][row]
    __shared__ float Bs[K1_KC * K1_COLS];     // Bs[e][col]
    __shared__ int   tk[K1_ROWS];

    const int tid  = threadIdx.x;
    const int row0 = blockIdx.x * K1_ROWS;
    const int c0   = blockIdx.y * K1_COLS;

    if (tid < K1_ROWS) tk[tid] = tokens[row0 + tid];

    const int rg = tid >> 5;
    const int cg = tid & 31;

    unsigned long long acc2[4][4];
    {
        const float4 bv = *(const float4*)&bias[c0 + cg * 4];
        #pragma unroll
        for (int rp = 0; rp < 4; rp++) {
            acc2[rp][0] = pack2(bv.x, bv.x);
            acc2[rp][1] = pack2(bv.y, bv.y);
            acc2[rp][2] = pack2(bv.z, bv.z);
            acc2[rp][3] = pack2(bv.w, bv.w);
        }
    }
    __syncthreads();

    for (int kc = 0; kc < EMB; kc += K1_KC) {
        for (int idx = tid; idx < K1_KC * K1_ROWS; idx += 256) {
            int e = idx >> 6, r = idx & 63;
            As[idx] = emb[(size_t)tk[r] * EMB + kc + e];
        }
        for (int idx = tid; idx < K1_KC * K1_COLS; idx += 256) {
            int e = idx >> 7, j = idx & 127;
            Bs[idx] = Wx[(kc + e) * GATES + c0 + j];
        }
        __syncthreads();

        #pragma unroll
        for (int k = 0; k < K1_KC; k++) {
            const ulonglong2* ap = (const ulonglong2*)&As[k * K1_ROWS + rg * 8];
            ulonglong2 a01 = ap[0];
            ulonglong2 a23 = ap[1];
            unsigned long long arp[4] = {a01.x, a01.y, a23.x, a23.y};

            float4 b4 = *(const float4*)&Bs[k * K1_COLS + cg * 4];
            unsigned long long bs[4] = {pack2(b4.x, b4.x), pack2(b4.y, b4.y),
                                        pack2(b4.z, b4.z), pack2(b4.w, b4.w)};
            #pragma unroll
            for (int rp = 0; rp < 4; rp++) {
                fma2(acc2[rp][0], arp[rp], bs[0]);
                fma2(acc2[rp][1], arp[rp], bs[1]);
                fma2(acc2[rp][2], arp[rp], bs[2]);
                fma2(acc2[rp][3], arp[rp], bs[3]);
            }
        }
        __syncthreads();
    }

    #pragma unroll
    for (int rp = 0; rp < 4; rp++) {
        float lo[4], hi[4];
        #pragma unroll
        for (int j = 0; j < 4; j++) unpack2(acc2[rp][j], lo[j], hi[j]);
        #pragma unroll
        for (int h = 0; h < 2; h++) {
            int gr = row0 + rg * 8 + rp * 2 + h;
            int b  = gr / SEQ;
            int t  = gr - b * SEQ;
            size_t off = ((size_t)t * BATCH + b) * GATES + c0 + cg * 4;
            float4 v = h ? make_float4(hi[0], hi[1], hi[2], hi[3])
                         : make_float4(lo[0], lo[1], lo[2], lo[3]);
            __stcs((float4*)&g_xz[off], v);
        }
    }
}

// ---------------------------------------------------------------------------
// K2: LSTM recurrence + dense head (v5)
//   128 CTAs x 8 batch rows, 512 threads = 16 warps, 4-way k-split.
//   Thread (u = tid&127, kh = tid>>7 in 0..3) accumulates z over 32 k's
//   [kh*32 .. kh*32+32) for unit u, 4 gates, all 8 rows (f32x2 row pairs):
//     - 20 k's: Wh from smem, one LDS.128 per k
//     - 12 k's: Wh REGISTER-RESIDENT (48 regs, loaded once)
//   ZERO global loads in the loop except the coalesced xz prefetch for the
//   thread's OWN 2 rows (2kh, 2kh+1). 3-slot partial exchange via smem.
//   Gate math uses __fdividef (MUFU.RCP) instead of div.rn.
// ---------------------------------------------------------------------------
#define K2_THREADS   512
#define K2_KQ        32   // k's per quarter
#define K2_SMEM_KQ   20   // smem-resident k's per quarter
#define K2_REG_KQ    12   // register-resident k's per quarter
#define K2_WHS_BYTES (4 * K2_SMEM_KQ * UNITS * 4 * 4)        // 163840
#define K2_HBUF_OFF  K2_WHS_BYTES
#define K2_PART_OFF  (K2_HBUF_OFF + 2 * UNITS * 8 * 4)       // +8192  = 172032
#define K2_D1S_OFF   (K2_PART_OFF + 4 * 3 * UNITS * 4 * 8)   // +49152 = 221184
#define K2_SMEM_TOT  (K2_D1S_OFF + 8 * DENSE * 4)            // 222208

__device__ __forceinline__ float fast_sigmoid(float x) {
    return __fdividef(1.0f, 1.0f + __expf(-x));
}
__device__ __forceinline__ float fast_tanh(float x) {
    x = fminf(fmaxf(x, -15.0f), 15.0f);
    float e = __expf(2.0f * x);
    return __fdividef(e - 1.0f, e + 1.0f);
}

__global__ __launch_bounds__(K2_THREADS, 1) void k2_lstm_head(
    const float* __restrict__ Wh,
    const float* __restrict__ W1, const float* __restrict__ b1,
    const float* __restrict__ W2, const float* __restrict__ b2,
    float* __restrict__ out)
{
    extern __shared__ unsigned char smem_raw[];
    float* whs = (float*)smem_raw;                                   // [80][128][4]
    float (*hbuf)[UNITS][8] = (float (*)[UNITS][8])(smem_raw + K2_HBUF_OFF);
    unsigned long long* part =
        (unsigned long long*)(smem_raw + K2_PART_OFF);  // [dest4][src3][u128][g4]
    float (*d1s)[DENSE] = (float (*)[DENSE])(smem_raw + K2_D1S_OFF);

    const int tid = threadIdx.x;
    const int u   = tid & 127;
    const int kh  = tid >> 7;          // 0..3, warp-uniform
    const int b0  = blockIdx.x * 8;

    // Stage smem Wh: slot s = q*20 + j -> k = q*32 + j,
    // whs[s][u][g] = Wh[k][g*128+u]  (coalesced in uu per (s,g))
    for (int idx = tid; idx < 4 * K2_SMEM_KQ * UNITS; idx += K2_THREADS) {
        int s  = idx >> 7;
        int uu = idx & 127;
        int k  = (s / K2_SMEM_KQ) * K2_KQ + (s % K2_SMEM_KQ);
        float4 w;
        w.x = Wh[(size_t)k * GATES + 0 * UNITS + uu];
        w.y = Wh[(size_t)k * GATES + 1 * UNITS + uu];
        w.z = Wh[(size_t)k * GATES + 2 * UNITS + uu];
        w.w = Wh[(size_t)k * GATES + 3 * UNITS + uu];
        *(float4*)&whs[(size_t)idx * 4] = w;
    }

    // Register-resident residual weights: k = kh*32 + 20 + j  (loaded ONCE)
    float wreg[K2_REG_KQ][4];
    {
        const float* wbase = Wh + (size_t)(kh * K2_KQ + K2_SMEM_KQ) * GATES + u;
        #pragma unroll
        for (int j = 0; j < K2_REG_KQ; j++)
            #pragma unroll
            for (int g = 0; g < 4; g++)
                wreg[j][g] = __ldg(wbase + (size_t)j * GATES + g * UNITS);
    }

    // zero h
    for (int i = tid; i < 2 * UNITS * 8; i += K2_THREADS)
        (&hbuf[0][0][0])[i] = 0.0f;
    float c[2] = {0.0f, 0.0f};          // cell state for rows 2kh, 2kh+1
    __syncthreads();

    const int k0 = kh * K2_KQ;
    const float4* wts = (const float4*)whs + (size_t)kh * K2_SMEM_KQ * UNITS + u;

    int cur = 0;
    for (int t = 0; t < SEQ; t++) {
        // Prefetch xz for OWNED rows (2kh, 2kh+1), coalesced in u.
        float xzv[2][4];
        {
            const float* xzb =
                &g_xz[((size_t)t * BATCH + b0 + 2 * kh) * GATES + u];
            #pragma unroll
            for (int g = 0; g < 4; g++) {
                xzv[0][g] = __ldcs(xzb + g * UNITS);
                xzv[1][g] = __ldcs(xzb + GATES + g * UNITS);
            }
        }

        unsigned long long z[4][4];
        #pragma unroll
        for (int rp = 0; rp < 4; rp++)
            #pragma unroll
            for (int g = 0; g < 4; g++) z[rp][g] = 0ull;

        const float (*hb)[8] = hbuf[cur];

        // smem-resident k's (w: 1 LDS.128; h: 2 broadcast LDS.128)
        #pragma unroll 5
        for (int kk = 0; kk < K2_SMEM_KQ; kk++) {
            const ulonglong2* hp2 = (const ulonglong2*)&hb[k0 + kk][0];
            ulonglong2 hA = hp2[0], hB = hp2[1];
            unsigned long long hp[4] = {hA.x, hA.y, hB.x, hB.y};

            float4 w4 = wts[(size_t)kk * UNITS];
            unsigned long long wp[4] = {pack2(w4.x, w4.x), pack2(w4.y, w4.y),
                                        pack2(w4.z, w4.z), pack2(w4.w, w4.w)};
            #pragma unroll
            for (int g = 0; g < 4; g++) {
                fma2(z[0][g], hp[0], wp[g]);
                fma2(z[1][g], hp[1], wp[g]);
                fma2(z[2][g], hp[2], wp[g]);
                fma2(z[3][g], hp[3], wp[g]);
            }
        }
        // register-resident k's (only h broadcast loads)
        #pragma unroll
        for (int j = 0; j < K2_REG_KQ; j++) {
            const ulonglong2* hp2 =
                (const ulonglong2*)&hb[k0 + K2_SMEM_KQ + j][0];
            ulonglong2 hA = hp2[0], hB = hp2[1];
            unsigned long long hp[4] = {hA.x, hA.y, hB.x, hB.y};
            #pragma unroll
            for (int g = 0; g < 4; g++) {
                unsigned long long wp = pack2(wreg[j][g], wreg[j][g]);
                fma2(z[0][g], hp[0], wp);
                fma2(z[1][g], hp[1], wp);
                fma2(z[2][g], hp[2], wp);
                fma2(z[3][g], hp[3], wp);
            }
        }

        // Ship the 3 non-owned row-pair partials to their owners.
        #pragma unroll
        for (int d = 0; d < 4; d++) {
            if (d == kh) continue;
            int slot = ((kh - d + 4) & 3) - 1;          // 0..2, unique per (d,src)
            ulonglong2* ps =
                (ulonglong2*)&part[(((size_t)d * 3 + slot) * UNITS + u) * 4];
            ps[0] = make_ulonglong2(z[d][0], z[d][1]);
            ps[1] = make_ulonglong2(z[d][2], z[d][3]);
        }
        __syncthreads();
        // Reduce owned row-pair kh
        #pragma unroll
        for (int slot = 0; slot < 3; slot++) {
            const ulonglong2* pm =
                (const ulonglong2*)&part[(((size_t)kh * 3 + slot) * UNITS + u) * 4];
            ulonglong2 p0 = pm[0], p1 = pm[1];
            add2(z[kh][0], p0.x); add2(z[kh][1], p0.y);
            add2(z[kh][2], p1.x); add2(z[kh][3], p1.y);
        }

        // gate math for rows 2kh, 2kh+1
        const int nxt = cur ^ 1;
        float hv[2];
        {
            float zi[2][4];
            #pragma unroll
            for (int g = 0; g < 4; g++) unpack2(z[kh][g], zi[0][g], zi[1][g]);
            #pragma unroll
            for (int h = 0; h < 2; h++) {
                float ig = fast_sigmoid(zi[h][0] + xzv[h][0]);
                float fg = fast_sigmoid(zi[h][1] + xzv[h][1]);
                float gg = fast_tanh   (zi[h][2] + xzv[h][2]);
                float og = fast_sigmoid(zi[h][3] + xzv[h][3]);
                float cc = fg * c[h] + ig * gg;
                c[h] = cc;
                hv[h] = og * fast_tanh(cc);
            }
        }
        *(float2*)&hbuf[nxt][u][2 * kh] = make_float2(hv[0], hv[1]);
        __syncthreads();
        cur = nxt;
    }

    // ---- dense head: relu(h @ W1 + b1) @ W2 + b2, softmax ----
    if (tid < 256) {
        int r = tid >> 5;            // 0..7
        int j = tid & 31;            // 0..31
        float a = b1[j];
        #pragma unroll 8
        for (int k = 0; k < UNITS; k++) a += hbuf[cur][k][r] * W1[k * DENSE + j];
        d1s[r][j] = fmaxf(a, 0.0f);
    }
    __syncthreads();
    if (tid < 8) {
        float l0 = b2[0], l1 = b2[1];
        #pragma unroll
        for (int j = 0; j < DENSE; j++) {
            float d = d1s[tid][j];
            l0 += d * W2[j * 2 + 0];
            l1 += d * W2[j * 2 + 1];
        }
        float m  = fmaxf(l0, l1);
        float e0 = __expf(l0 - m), e1 = __expf(l1 - m);
        float s  = __fdividef(1.0f, e0 + e1);
        out[(b0 + tid) * 2 + 0] = e0 * s;
        out[(b0 + tid) * 2 + 1] = e1 * s;
    }
}

// ---------------------------------------------------------------------------
extern "C" void kernel_launch(void* const* d_in, const int* in_sizes, int n_in,
                              void* d_out, int out_size)
{
    const int*   tokens = (const int*)  d_in[0];
    const float* emb    = (const float*)d_in[1];
    const float* Wx     = (const float*)d_in[2];
    const float* Wh     = (const float*)d_in[3];
    const float* lb     = (const float*)d_in[4];
    const float* W1     = (const float*)d_in[5];
    const float* b1     = (const float*)d_in[6];
    const float* W2     = (const float*)d_in[7];
    const float* b2     = (const float*)d_in[8];
    float* out = (float*)d_out;

    cudaFuncSetAttribute(k2_lstm_head,
                         cudaFuncAttributeMaxDynamicSharedMemorySize, K2_SMEM_TOT);

    dim3 g1(BATCH * SEQ / K1_ROWS, GATES / K1_COLS);   // (4000, 4)
    k1_embed_proj<<<g1, 256>>>(tokens, emb, Wx, lb);
    k2_lstm_head<<<BATCH / 8, K2_THREADS, K2_SMEM_TOT>>>(Wh, W1, b1, W2, b2, out);
}

// round 11
// speedup vs baseline: 1.3338x; 1.0721x over previous
#include <cuda_runtime.h>
#include <math.h>

#define BATCH 1024
#define SEQ   250
#define EMB   100
#define UNITS 128
#define GATES 512   // 4*UNITS, gate order i,f,g,o
#define DENSE 32

// Scratch: xz = emb[tokens] @ Wx + b, layout [t][b][512] (524 MB)
__device__ float g_xz[(size_t)SEQ * BATCH * GATES];

// ---- packed f32x2 helpers (sm_100a) --------------------------------------
__device__ __forceinline__ unsigned long long pack2(float a, float b) {
    unsigned long long r;
    asm("mov.b64 %0, {%1, %2};" : "=l"(r) : "f"(a), "f"(b));
    return r;
}
__device__ __forceinline__ void unpack2(unsigned long long v, float& a, float& b) {
    asm("mov.b64 {%0, %1}, %2;" : "=f"(a), "=f"(b) : "l"(v));
}
__device__ __forceinline__ void fma2(unsigned long long& d, unsigned long long a,
                                     unsigned long long b) {
    asm("fma.rn.f32x2 %0, %1, %2, %0;" : "+l"(d) : "l"(a), "l"(b));
}
__device__ __forceinline__ void add2(unsigned long long& d, unsigned long long a) {
    asm("add.rn.f32x2 %0, %0, %1;" : "+l"(d) : "l"(a));
}

// ---------------------------------------------------------------------------
// K1: embedding gather + input projection GEMM (v2)
//   A staged FULL-K once via float4 emb loads (16B sectors, conflict-free STS)
//   instead of scattered 4B gathers; Bs chunked as before.
// ---------------------------------------------------------------------------
#define K1_ROWS 64
#define K1_COLS 128
#define K1_KC   25

__global__ __launch_bounds__(256) void k1_embed_proj(
    const int* __restrict__ tokens, const float* __restrict__ emb,
    const float* __restrict__ Wx, const float* __restrict__ bias)
{
    __shared__ float As[EMB][K1_ROWS];        // [e][row], 25.6 KB
    __shared__ float Bs[K1_KC * K1_COLS];     // [e][col], 12.8 KB
    __shared__ int   tk[K1_ROWS];

    const int tid  = threadIdx.x;
    const int row0 = blockIdx.x * K1_ROWS;
    const int c0   = blockIdx.y * K1_COLS;

    if (tid < K1_ROWS) tk[tid] = tokens[row0 + tid];

    const int rg = tid >> 5;
    const int cg = tid & 31;

    unsigned long long acc2[4][4];
    {
        const float4 bv = *(const float4*)&bias[c0 + cg * 4];
        #pragma unroll
        for (int rp = 0; rp < 4; rp++) {
            acc2[rp][0] = pack2(bv.x, bv.x);
            acc2[rp][1] = pack2(bv.y, bv.y);
            acc2[rp][2] = pack2(bv.z, bv.z);
            acc2[rp][3] = pack2(bv.w, bv.w);
        }
    }
    __syncthreads();  // tk visible

    // Gather A full-K: float4 over emb rows (100 floats = 25 float4, 16B aligned)
    // lanes iterate r fastest -> conflict-free STS, scattered 16B LDG (2 sectors)
    {
        const float4* emb4 = (const float4*)emb;
        for (int idx = tid; idx < K1_ROWS * (EMB / 4); idx += 256) {
            int r = idx & (K1_ROWS - 1);
            int q = idx >> 6;                  // float4 index 0..24
            float4 v = emb4[(size_t)tk[r] * (EMB / 4) + q];
            As[q * 4 + 0][r] = v.x;
            As[q * 4 + 1][r] = v.y;
            As[q * 4 + 2][r] = v.z;
            As[q * 4 + 3][r] = v.w;
        }
    }

    for (int kc = 0; kc < EMB; kc += K1_KC) {
        for (int idx = tid; idx < K1_KC * K1_COLS; idx += 256) {
            int e = idx >> 7, j = idx & 127;
            Bs[idx] = Wx[(kc + e) * GATES + c0 + j];
        }
        __syncthreads();   // covers As on first iteration too

        #pragma unroll
        for (int k = 0; k < K1_KC; k++) {
            const ulonglong2* ap = (const ulonglong2*)&As[kc + k][rg * 8];
            ulonglong2 a01 = ap[0];
            ulonglong2 a23 = ap[1];
            unsigned long long arp[4] = {a01.x, a01.y, a23.x, a23.y};

            float4 b4 = *(const float4*)&Bs[k * K1_COLS + cg * 4];
            unsigned long long bs[4] = {pack2(b4.x, b4.x), pack2(b4.y, b4.y),
                                        pack2(b4.z, b4.z), pack2(b4.w, b4.w)};
            #pragma unroll
            for (int rp = 0; rp < 4; rp++) {
                fma2(acc2[rp][0], arp[rp], bs[0]);
                fma2(acc2[rp][1], arp[rp], bs[1]);
                fma2(acc2[rp][2], arp[rp], bs[2]);
                fma2(acc2[rp][3], arp[rp], bs[3]);
            }
        }
        __syncthreads();
    }

    #pragma unroll
    for (int rp = 0; rp < 4; rp++) {
        float lo[4], hi[4];
        #pragma unroll
        for (int j = 0; j < 4; j++) unpack2(acc2[rp][j], lo[j], hi[j]);
        #pragma unroll
        for (int h = 0; h < 2; h++) {
            int gr = row0 + rg * 8 + rp * 2 + h;
            int b  = gr / SEQ;
            int t  = gr - b * SEQ;
            size_t off = ((size_t)t * BATCH + b) * GATES + c0 + cg * 4;
            float4 v = h ? make_float4(hi[0], hi[1], hi[2], hi[3])
                         : make_float4(lo[0], lo[1], lo[2], lo[3]);
            __stcs((float4*)&g_xz[off], v);
        }
    }
}

// ---------------------------------------------------------------------------
// K2: LSTM recurrence + dense head (v6)
//   Same structure as v5 (512 thr, 4-way k-split, zero-LDG loop, 3-slot
//   exchange) but the gate tail uses tanh.approx.f32:
//   sigma(x) = 0.5*tanh(0.5x)+0.5 — MUFU count halved, no RCP chains.
// ---------------------------------------------------------------------------
#define K2_THREADS   512
#define K2_KQ        32   // k's per quarter
#define K2_SMEM_KQ   20   // smem-resident k's per quarter
#define K2_REG_KQ    12   // register-resident k's per quarter
#define K2_WHS_BYTES (4 * K2_SMEM_KQ * UNITS * 4 * 4)        // 163840
#define K2_HBUF_OFF  K2_WHS_BYTES
#define K2_PART_OFF  (K2_HBUF_OFF + 2 * UNITS * 8 * 4)       // +8192  = 172032
#define K2_D1S_OFF   (K2_PART_OFF + 4 * 3 * UNITS * 4 * 8)   // +49152 = 221184
#define K2_SMEM_TOT  (K2_D1S_OFF + 8 * DENSE * 4)            // 222208

__device__ __forceinline__ float tanh_fast(float x) {
    float r;
    asm("tanh.approx.f32 %0, %1;" : "=f"(r) : "f"(x));
    return r;
}
__device__ __forceinline__ float sigm_fast(float x) {
    return fmaf(0.5f, tanh_fast(0.5f * x), 0.5f);
}

__global__ __launch_bounds__(K2_THREADS, 1) void k2_lstm_head(
    const float* __restrict__ Wh,
    const float* __restrict__ W1, const float* __restrict__ b1,
    const float* __restrict__ W2, const float* __restrict__ b2,
    float* __restrict__ out)
{
    extern __shared__ unsigned char smem_raw[];
    float* whs = (float*)smem_raw;                                   // [80][128][4]
    float (*hbuf)[UNITS][8] = (float (*)[UNITS][8])(smem_raw + K2_HBUF_OFF);
    unsigned long long* part =
        (unsigned long long*)(smem_raw + K2_PART_OFF);  // [dest4][src3][u128][g4]
    float (*d1s)[DENSE] = (float (*)[DENSE])(smem_raw + K2_D1S_OFF);

    const int tid = threadIdx.x;
    const int u   = tid & 127;
    const int kh  = tid >> 7;          // 0..3, warp-uniform
    const int b0  = blockIdx.x * 8;

    // Stage smem Wh: slot s = q*20 + j -> k = q*32 + j,
    // whs[s][u][g] = Wh[k][g*128+u]
    for (int idx = tid; idx < 4 * K2_SMEM_KQ * UNITS; idx += K2_THREADS) {
        int s  = idx >> 7;
        int uu = idx & 127;
        int k  = (s / K2_SMEM_KQ) * K2_KQ + (s % K2_SMEM_KQ);
        float4 w;
        w.x = Wh[(size_t)k * GATES + 0 * UNITS + uu];
        w.y = Wh[(size_t)k * GATES + 1 * UNITS + uu];
        w.z = Wh[(size_t)k * GATES + 2 * UNITS + uu];
        w.w = Wh[(size_t)k * GATES + 3 * UNITS + uu];
        *(float4*)&whs[(size_t)idx * 4] = w;
    }

    // Register-resident residual weights: k = kh*32 + 20 + j (loaded ONCE)
    float wreg[K2_REG_KQ][4];
    {
        const float* wbase = Wh + (size_t)(kh * K2_KQ + K2_SMEM_KQ) * GATES + u;
        #pragma unroll
        for (int j = 0; j < K2_REG_KQ; j++)
            #pragma unroll
            for (int g = 0; g < 4; g++)
                wreg[j][g] = __ldg(wbase + (size_t)j * GATES + g * UNITS);
    }

    // zero h
    for (int i = tid; i < 2 * UNITS * 8; i += K2_THREADS)
        (&hbuf[0][0][0])[i] = 0.0f;
    float c[2] = {0.0f, 0.0f};          // cell state for rows 2kh, 2kh+1
    __syncthreads();

    const int k0 = kh * K2_KQ;
    const float4* wts = (const float4*)whs + (size_t)kh * K2_SMEM_KQ * UNITS + u;

    int cur = 0;
    for (int t = 0; t < SEQ; t++) {
        // Prefetch xz for OWNED rows (2kh, 2kh+1), coalesced in u.
        float xzv[2][4];
        {
            const float* xzb =
                &g_xz[((size_t)t * BATCH + b0 + 2 * kh) * GATES + u];
            #pragma unroll
            for (int g = 0; g < 4; g++) {
                xzv[0][g] = __ldcs(xzb + g * UNITS);
                xzv[1][g] = __ldcs(xzb + GATES + g * UNITS);
            }
        }

        unsigned long long z[4][4];
        #pragma unroll
        for (int rp = 0; rp < 4; rp++)
            #pragma unroll
            for (int g = 0; g < 4; g++) z[rp][g] = 0ull;

        const float (*hb)[8] = hbuf[cur];

        // smem-resident k's (w: 1 LDS.128; h: 2 broadcast LDS.128)
        #pragma unroll 5
        for (int kk = 0; kk < K2_SMEM_KQ; kk++) {
            const ulonglong2* hp2 = (const ulonglong2*)&hb[k0 + kk][0];
            ulonglong2 hA = hp2[0], hB = hp2[1];
            unsigned long long hp[4] = {hA.x, hA.y, hB.x, hB.y};

            float4 w4 = wts[(size_t)kk * UNITS];
            unsigned long long wp[4] = {pack2(w4.x, w4.x), pack2(w4.y, w4.y),
                                        pack2(w4.z, w4.z), pack2(w4.w, w4.w)};
            #pragma unroll
            for (int g = 0; g < 4; g++) {
                fma2(z[0][g], hp[0], wp[g]);
                fma2(z[1][g], hp[1], wp[g]);
                fma2(z[2][g], hp[2], wp[g]);
                fma2(z[3][g], hp[3], wp[g]);
            }
        }
        // register-resident k's (only h broadcast loads)
        #pragma unroll
        for (int j = 0; j < K2_REG_KQ; j++) {
            const ulonglong2* hp2 =
                (const ulonglong2*)&hb[k0 + K2_SMEM_KQ + j][0];
            ulonglong2 hA = hp2[0], hB = hp2[1];
            unsigned long long hp[4] = {hA.x, hA.y, hB.x, hB.y};
            #pragma unroll
            for (int g = 0; g < 4; g++) {
                unsigned long long wp = pack2(wreg[j][g], wreg[j][g]);
                fma2(z[0][g], hp[0], wp);
                fma2(z[1][g], hp[1], wp);
                fma2(z[2][g], hp[2], wp);
                fma2(z[3][g], hp[3], wp);
            }
        }

        // Ship the 3 non-owned row-pair partials to their owners.
        #pragma unroll
        for (int d = 0; d < 4; d++) {
            if (d == kh) continue;
            int slot = ((kh - d + 4) & 3) - 1;          // 0..2, unique per (d,src)
            ulonglong2* ps =
                (ulonglong2*)&part[(((size_t)d * 3 + slot) * UNITS + u) * 4];
            ps[0] = make_ulonglong2(z[d][0], z[d][1]);
            ps[1] = make_ulonglong2(z[d][2], z[d][3]);
        }
        __syncthreads();
        // Reduce owned row-pair kh
        #pragma unroll
        for (int slot = 0; slot < 3; slot++) {
            const ulonglong2* pm =
                (const ulonglong2*)&part[(((size_t)kh * 3 + slot) * UNITS + u) * 4];
            ulonglong2 p0 = pm[0], p1 = pm[1];
            add2(z[kh][0], p0.x); add2(z[kh][1], p0.y);
            add2(z[kh][2], p1.x); add2(z[kh][3], p1.y);
        }

        // gate math for rows 2kh, 2kh+1 (tanh.approx-based)
        const int nxt = cur ^ 1;
        float hv[2];
        {
            float zi[2][4];
            #pragma unroll
            for (int g = 0; g < 4; g++) unpack2(z[kh][g], zi[0][g], zi[1][g]);
            #pragma unroll
            for (int h = 0; h < 2; h++) {
                float ig = sigm_fast(zi[h][0] + xzv[h][0]);
                float fg = sigm_fast(zi[h][1] + xzv[h][1]);
                float gg = tanh_fast(zi[h][2] + xzv[h][2]);
                float og = sigm_fast(zi[h][3] + xzv[h][3]);
                float cc = fg * c[h] + ig * gg;
                c[h] = cc;
                hv[h] = og * tanh_fast(cc);
            }
        }
        *(float2*)&hbuf[nxt][u][2 * kh] = make_float2(hv[0], hv[1]);
        __syncthreads();
        cur = nxt;
    }

    // ---- dense head: relu(h @ W1 + b1) @ W2 + b2, softmax ----
    if (tid < 256) {
        int r = tid >> 5;            // 0..7
        int j = tid & 31;            // 0..31
        float a = b1[j];
        #pragma unroll 8
        for (int k = 0; k < UNITS; k++) a += hbuf[cur][k][r] * W1[k * DENSE + j];
        d1s[r][j] = fmaxf(a, 0.0f);
    }
    __syncthreads();
    if (tid < 8) {
        float l0 = b2[0], l1 = b2[1];
        #pragma unroll
        for (int j = 0; j < DENSE; j++) {
            float d = d1s[tid][j];
            l0 += d * W2[j * 2 + 0];
            l1 += d * W2[j * 2 + 1];
        }
        float m  = fmaxf(l0, l1);
        float e0 = __expf(l0 - m), e1 = __expf(l1 - m);
        float s  = __fdividef(1.0f, e0 + e1);
        out[(b0 + tid) * 2 + 0] = e0 * s;
        out[(b0 + tid) * 2 + 1] = e1 * s;
    }
}

// ---------------------------------------------------------------------------
extern "C" void kernel_launch(void* const* d_in, const int* in_sizes, int n_in,
                              void* d_out, int out_size)
{
    const int*   tokens = (const int*)  d_in[0];
    const float* emb    = (const float*)d_in[1];
    const float* Wx     = (const float*)d_in[2];
    const float* Wh     = (const float*)d_in[3];
    const float* lb     = (const float*)d_in[4];
    const float* W1     = (const float*)d_in[5];
    const float* b1     = (const float*)d_in[6];
    const float* W2     = (const float*)d_in[7];
    const float* b2     = (const float*)d_in[8];
    float* out = (float*)d_out;

    cudaFuncSetAttribute(k2_lstm_head,
                         cudaFuncAttributeMaxDynamicSharedMemorySize, K2_SMEM_TOT);

    dim3 g1(BATCH * SEQ / K1_ROWS, GATES / K1_COLS);   // (4000, 4)
    k1_embed_proj<<<g1, 256>>>(tokens, emb, Wx, lb);
    k2_lstm_head<<<BATCH / 8, K2_THREADS, K2_SMEM_TOT>>>(Wh, W1, b1, W2, b2, out);
}

// round 12
// speedup vs baseline: 1.5081x; 1.1307x over previous
#include <cuda_runtime.h>
#include <cuda_bf16.h>
#include <math.h>

#define BATCH 1024
#define SEQ   250
#define EMB   100
#define UNITS 128
#define GATES 512   // 4*UNITS, gate order i,f,g,o
#define DENSE 32

// Scratch: xz = emb[tokens] @ Wx + b, layout [t][b][512], bf16 (262 MB)
__device__ unsigned short g_xz[(size_t)SEQ * BATCH * GATES];

// ---- packed f32x2 helpers (sm_100a) --------------------------------------
__device__ __forceinline__ unsigned long long pack2(float a, float b) {
    unsigned long long r;
    asm("mov.b64 %0, {%1, %2};" : "=l"(r) : "f"(a), "f"(b));
    return r;
}
__device__ __forceinline__ void unpack2(unsigned long long v, float& a, float& b) {
    asm("mov.b64 {%0, %1}, %2;" : "=f"(a), "=f"(b) : "l"(v));
}
__device__ __forceinline__ void fma2(unsigned long long& d, unsigned long long a,
                                     unsigned long long b) {
    asm("fma.rn.f32x2 %0, %1, %2, %0;" : "+l"(d) : "l"(a), "l"(b));
}
__device__ __forceinline__ void add2(unsigned long long& d, unsigned long long a) {
    asm("add.rn.f32x2 %0, %0, %1;" : "+l"(d) : "l"(a));
}
__device__ __forceinline__ float bf2f(unsigned short v) {
    return __uint_as_float(((unsigned int)v) << 16);
}

// ---- mma.sync bf16 helpers -----------------------------------------------
__device__ __forceinline__ void ldsm_x4(unsigned& r0, unsigned& r1,
                                        unsigned& r2, unsigned& r3, unsigned addr) {
    asm volatile("ldmatrix.sync.aligned.m8n8.x4.shared.b16 {%0,%1,%2,%3}, [%4];"
                 : "=r"(r0), "=r"(r1), "=r"(r2), "=r"(r3) : "r"(addr));
}
__device__ __forceinline__ void ldsm_x2(unsigned& r0, unsigned& r1, unsigned addr) {
    asm volatile("ldmatrix.sync.aligned.m8n8.x2.shared.b16 {%0,%1}, [%2];"
                 : "=r"(r0), "=r"(r1) : "r"(addr));
}
__device__ __forceinline__ void mma16816(float* d,
                                         unsigned a0, unsigned a1, unsigned a2, unsigned a3,
                                         unsigned b0, unsigned b1) {
    asm volatile("mma.sync.aligned.m16n8k16.row.col.f32.bf16.bf16.f32 "
                 "{%0,%1,%2,%3}, {%4,%5,%6,%7}, {%8,%9}, {%0,%1,%2,%3};"
                 : "+f"(d[0]), "+f"(d[1]), "+f"(d[2]), "+f"(d[3])
                 : "r"(a0), "r"(a1), "r"(a2), "r"(a3), "r"(b0), "r"(b1));
}

// ---------------------------------------------------------------------------
// K1 (v3): embedding gather + input projection via bf16 mma.sync
//   CTA tile 64 rows x 128 cols, K = 100 padded to 112 (7 x k16).
//   As[64][120] bf16 (240B stride: ldmatrix conflict-free), Bs[128][120]
//   holds Wx TRANSPOSED ([n][k]) so both operands use non-trans ldmatrix.
//   8 warps: warp (rw = wid&3, cw = wid>>2) covers (m16, n64) = 8 n8-tiles.
//   Bias folded into accumulator init; epilogue stores bf16x2 pairs into
//   g_xz[t][b][512].
// ---------------------------------------------------------------------------
#define K1_ROWS 64
#define K1_COLS 128
#define K1_KPAD 112
#define K1_KSTR 120   // smem row stride in bf16 elems (240 B)

__global__ __launch_bounds__(256) void k1_embed_proj(
    const int* __restrict__ tokens, const float* __restrict__ emb,
    const float* __restrict__ Wx, const float* __restrict__ bias)
{
    __shared__ __align__(16) __nv_bfloat16 As[K1_ROWS][K1_KSTR];  // 15360 B
    __shared__ __align__(16) __nv_bfloat16 Bs[K1_COLS][K1_KSTR];  // 30720 B
    __shared__ int tk[K1_ROWS];

    const int tid  = threadIdx.x;
    const int row0 = blockIdx.x * K1_ROWS;    // global row = b*SEQ + t
    const int c0   = blockIdx.y * K1_COLS;

    if (tid < K1_ROWS) tk[tid] = tokens[row0 + tid];
    __syncthreads();

    // ---- stage A: gathered emb rows -> bf16, [r][k] ----
    {
        const float4* emb4 = (const float4*)emb;
        for (int idx = tid; idx < K1_ROWS * (EMB / 4); idx += 256) {
            int r = idx & 63;
            int q = idx >> 6;                 // float4 index 0..24
            float4 v = emb4[(size_t)tk[r] * (EMB / 4) + q];
            *(__nv_bfloat162*)&As[r][q * 4]     = __floats2bfloat162_rn(v.x, v.y);
            *(__nv_bfloat162*)&As[r][q * 4 + 2] = __floats2bfloat162_rn(v.z, v.w);
        }
        // zero K tail 100..119
        for (int idx = tid; idx < K1_ROWS * 10; idx += 256) {
            int r = idx / 10, j = idx % 10;
            *(__nv_bfloat162*)&As[r][EMB + 2 * j] = __floats2bfloat162_rn(0.f, 0.f);
        }
    }
    // ---- stage B: Wx transposed -> Bs[n][k] bf16 ----
    {
        for (int idx = tid; idx < EMB * K1_COLS; idx += 256) {
            int e = idx >> 7, n = idx & 127;
            Bs[n][e] = __float2bfloat16(Wx[(size_t)e * GATES + c0 + n]);
        }
        for (int idx = tid; idx < K1_COLS * 10; idx += 256) {
            int n = idx / 10, j = idx % 10;
            *(__nv_bfloat162*)&Bs[n][EMB + 2 * j] = __floats2bfloat162_rn(0.f, 0.f);
        }
    }
    __syncthreads();

    const int wid  = tid >> 5;
    const int lane = tid & 31;
    const int rw   = wid & 3;     // row-warp: rows rw*16..+15
    const int cw   = wid >> 2;    // col-warp: cols cw*64..+63

    // accumulators, bias-initialized: acc[j] = {c0,c1 (row lo), c2,c3 (row hi)}
    float acc[8][4];
    #pragma unroll
    for (int j = 0; j < 8; j++) {
        float2 bv = *(const float2*)&bias[c0 + cw * 64 + j * 8 + (lane & 3) * 2];
        acc[j][0] = bv.x; acc[j][1] = bv.y;
        acc[j][2] = bv.x; acc[j][3] = bv.y;
    }

    // ldmatrix base addresses (byte offsets into shared space)
    unsigned a_base = (unsigned)__cvta_generic_to_shared(
                          &As[rw * 16 + (lane & 15)][0]) + ((lane >> 4) * 8) * 2;
    unsigned b_base = (unsigned)__cvta_generic_to_shared(
                          &Bs[cw * 64 + (lane & 7)][0]) + (((lane >> 3) & 1) * 8) * 2;

    #pragma unroll
    for (int k = 0; k < K1_KPAD / 16; k++) {
        unsigned a0, a1, a2, a3;
        ldsm_x4(a0, a1, a2, a3, a_base + k * 32);
        #pragma unroll
        for (int j = 0; j < 8; j++) {
            unsigned b0, b1;
            ldsm_x2(b0, b1, b_base + j * (8 * K1_KSTR * 2) + k * 32);
            mma16816(acc[j], a0, a1, a2, a3, b0, b1);
        }
    }

    // ---- epilogue: bf16 pairs into g_xz[t][b][512] ----
    {
        int r_lo = row0 + rw * 16 + (lane >> 2);
        int r_hi = r_lo + 8;
        int b_lo = r_lo / SEQ, t_lo = r_lo - b_lo * SEQ;
        int b_hi = r_hi / SEQ, t_hi = r_hi - b_hi * SEQ;
        size_t base_lo = ((size_t)t_lo * BATCH + b_lo) * GATES;
        size_t base_hi = ((size_t)t_hi * BATCH + b_hi) * GATES;
        int colb = c0 + cw * 64 + (lane & 3) * 2;
        #pragma unroll
        for (int j = 0; j < 8; j++) {
            int col = colb + j * 8;
            *(__nv_bfloat162*)&g_xz[base_lo + col] =
                __floats2bfloat162_rn(acc[j][0], acc[j][1]);
            *(__nv_bfloat162*)&g_xz[base_hi + col] =
                __floats2bfloat162_rn(acc[j][2], acc[j][3]);
        }
    }
}

// ---------------------------------------------------------------------------
// K2: LSTM recurrence + dense head (v6 + bf16 xz reads; otherwise unchanged)
// ---------------------------------------------------------------------------
#define K2_THREADS   512
#define K2_KQ        32   // k's per quarter
#define K2_SMEM_KQ   20   // smem-resident k's per quarter
#define K2_REG_KQ    12   // register-resident k's per quarter
#define K2_WHS_BYTES (4 * K2_SMEM_KQ * UNITS * 4 * 4)        // 163840
#define K2_HBUF_OFF  K2_WHS_BYTES
#define K2_PART_OFF  (K2_HBUF_OFF + 2 * UNITS * 8 * 4)       // +8192  = 172032
#define K2_D1S_OFF   (K2_PART_OFF + 4 * 3 * UNITS * 4 * 8)   // +49152 = 221184
#define K2_SMEM_TOT  (K2_D1S_OFF + 8 * DENSE * 4)            // 222208

__device__ __forceinline__ float tanh_fast(float x) {
    float r;
    asm("tanh.approx.f32 %0, %1;" : "=f"(r) : "f"(x));
    return r;
}
__device__ __forceinline__ float sigm_fast(float x) {
    return fmaf(0.5f, tanh_fast(0.5f * x), 0.5f);
}

__global__ __launch_bounds__(K2_THREADS, 1) void k2_lstm_head(
    const float* __restrict__ Wh,
    const float* __restrict__ W1, const float* __restrict__ b1,
    const float* __restrict__ W2, const float* __restrict__ b2,
    float* __restrict__ out)
{
    extern __shared__ unsigned char smem_raw[];
    float* whs = (float*)smem_raw;                                   // [80][128][4]
    float (*hbuf)[UNITS][8] = (float (*)[UNITS][8])(smem_raw + K2_HBUF_OFF);
    unsigned long long* part =
        (unsigned long long*)(smem_raw + K2_PART_OFF);  // [dest4][src3][u128][g4]
    float (*d1s)[DENSE] = (float (*)[DENSE])(smem_raw + K2_D1S_OFF);

    const int tid = threadIdx.x;
    const int u   = tid & 127;
    const int kh  = tid >> 7;          // 0..3, warp-uniform
    const int b0  = blockIdx.x * 8;

    // Stage smem Wh: slot s = q*20 + j -> k = q*32 + j, whs[s][u][g]
    for (int idx = tid; idx < 4 * K2_SMEM_KQ * UNITS; idx += K2_THREADS) {
        int s  = idx >> 7;
        int uu = idx & 127;
        int k  = (s / K2_SMEM_KQ) * K2_KQ + (s % K2_SMEM_KQ);
        float4 w;
        w.x = Wh[(size_t)k * GATES + 0 * UNITS + uu];
        w.y = Wh[(size_t)k * GATES + 1 * UNITS + uu];
        w.z = Wh[(size_t)k * GATES + 2 * UNITS + uu];
        w.w = Wh[(size_t)k * GATES + 3 * UNITS + uu];
        *(float4*)&whs[(size_t)idx * 4] = w;
    }

    // Register-resident residual weights: k = kh*32 + 20 + j (loaded ONCE)
    float wreg[K2_REG_KQ][4];
    {
        const float* wbase = Wh + (size_t)(kh * K2_KQ + K2_SMEM_KQ) * GATES + u;
        #pragma unroll
        for (int j = 0; j < K2_REG_KQ; j++)
            #pragma unroll
            for (int g = 0; g < 4; g++)
                wreg[j][g] = __ldg(wbase + (size_t)j * GATES + g * UNITS);
    }

    // zero h
    for (int i = tid; i < 2 * UNITS * 8; i += K2_THREADS)
        (&hbuf[0][0][0])[i] = 0.0f;
    float c[2] = {0.0f, 0.0f};          // cell state for rows 2kh, 2kh+1
    __syncthreads();

    const int k0 = kh * K2_KQ;
    const float4* wts = (const float4*)whs + (size_t)kh * K2_SMEM_KQ * UNITS + u;

    int cur = 0;
    for (int t = 0; t < SEQ; t++) {
        // Prefetch xz (bf16) for OWNED rows (2kh, 2kh+1), coalesced in u.
        float xzv[2][4];
        {
            const unsigned short* xzb =
                &g_xz[((size_t)t * BATCH + b0 + 2 * kh) * GATES + u];
            #pragma unroll
            for (int g = 0; g < 4; g++) {
                xzv[0][g] = bf2f(xzb[g * UNITS]);
                xzv[1][g] = bf2f(xzb[GATES + g * UNITS]);
            }
        }

        unsigned long long z[4][4];
        #pragma unroll
        for (int rp = 0; rp < 4; rp++)
            #pragma unroll
            for (int g = 0; g < 4; g++) z[rp][g] = 0ull;

        const float (*hb)[8] = hbuf[cur];

        // smem-resident k's (w: 1 LDS.128; h: 2 broadcast LDS.128)
        #pragma unroll 5
        for (int kk = 0; kk < K2_SMEM_KQ; kk++) {
            const ulonglong2* hp2 = (const ulonglong2*)&hb[k0 + kk][0];
            ulonglong2 hA = hp2[0], hB = hp2[1];
            unsigned long long hp[4] = {hA.x, hA.y, hB.x, hB.y};

            float4 w4 = wts[(size_t)kk * UNITS];
            unsigned long long wp[4] = {pack2(w4.x, w4.x), pack2(w4.y, w4.y),
                                        pack2(w4.z, w4.z), pack2(w4.w, w4.w)};
            #pragma unroll
            for (int g = 0; g < 4; g++) {
                fma2(z[0][g], hp[0], wp[g]);
                fma2(z[1][g], hp[1], wp[g]);
                fma2(z[2][g], hp[2], wp[g]);
                fma2(z[3][g], hp[3], wp[g]);
            }
        }
        // register-resident k's (only h broadcast loads)
        #pragma unroll
        for (int j = 0; j < K2_REG_KQ; j++) {
            const ulonglong2* hp2 =
                (const ulonglong2*)&hb[k0 + K2_SMEM_KQ + j][0];
            ulonglong2 hA = hp2[0], hB = hp2[1];
            unsigned long long hp[4] = {hA.x, hA.y, hB.x, hB.y};
            #pragma unroll
            for (int g = 0; g < 4; g++) {
                unsigned long long wp = pack2(wreg[j][g], wreg[j][g]);
                fma2(z[0][g], hp[0], wp);
                fma2(z[1][g], hp[1], wp);
                fma2(z[2][g], hp[2], wp);
                fma2(z[3][g], hp[3], wp);
            }
        }

        // Ship the 3 non-owned row-pair partials to their owners.
        #pragma unroll
        for (int d = 0; d < 4; d++) {
            if (d == kh) continue;
            int slot = ((kh - d + 4) & 3) - 1;          // 0..2, unique per (d,src)
            ulonglong2* ps =
                (ulonglong2*)&part[(((size_t)d * 3 + slot) * UNITS + u) * 4];
            ps[0] = make_ulonglong2(z[d][0], z[d][1]);
            ps[1] = make_ulonglong2(z[d][2], z[d][3]);
        }
        __syncthreads();
        // Reduce owned row-pair kh
        #pragma unroll
        for (int slot = 0; slot < 3; slot++) {
            const ulonglong2* pm =
                (const ulonglong2*)&part[(((size_t)kh * 3 + slot) * UNITS + u) * 4];
            ulonglong2 p0 = pm[0], p1 = pm[1];
            add2(z[kh][0], p0.x); add2(z[kh][1], p0.y);
            add2(z[kh][2], p1.x); add2(z[kh][3], p1.y);
        }

        // gate math for rows 2kh, 2kh+1 (tanh.approx-based)
        const int nxt = cur ^ 1;
        float hv[2];
        {
            float zi[2][4];
            #pragma unroll
            for (int g = 0; g < 4; g++) unpack2(z[kh][g], zi[0][g], zi[1][g]);
            #pragma unroll
            for (int h = 0; h < 2; h++) {
                float ig = sigm_fast(zi[h][0] + xzv[h][0]);
                float fg = sigm_fast(zi[h][1] + xzv[h][1]);
                float gg = tanh_fast(zi[h][2] + xzv[h][2]);
                float og = sigm_fast(zi[h][3] + xzv[h][3]);
                float cc = fg * c[h] + ig * gg;
                c[h] = cc;
                hv[h] = og * tanh_fast(cc);
            }
        }
        *(float2*)&hbuf[nxt][u][2 * kh] = make_float2(hv[0], hv[1]);
        __syncthreads();
        cur = nxt;
    }

    // ---- dense head: relu(h @ W1 + b1) @ W2 + b2, softmax ----
    if (tid < 256) {
        int r = tid >> 5;            // 0..7
        int j = tid & 31;            // 0..31
        float a = b1[j];
        #pragma unroll 8
        for (int k = 0; k < UNITS; k++) a += hbuf[cur][k][r] * W1[k * DENSE + j];
        d1s[r][j] = fmaxf(a, 0.0f);
    }
    __syncthreads();
    if (tid < 8) {
        float l0 = b2[0], l1 = b2[1];
        #pragma unroll
        for (int j = 0; j < DENSE; j++) {
            float d = d1s[tid][j];
            l0 += d * W2[j * 2 + 0];
            l1 += d * W2[j * 2 + 1];
        }
        float m  = fmaxf(l0, l1);
        float e0 = __expf(l0 - m), e1 = __expf(l1 - m);
        float s  = __fdividef(1.0f, e0 + e1);
        out[(b0 + tid) * 2 + 0] = e0 * s;
        out[(b0 + tid) * 2 + 1] = e1 * s;
    }
}

// ---------------------------------------------------------------------------
extern "C" void kernel_launch(void* const* d_in, const int* in_sizes, int n_in,
                              void* d_out, int out_size)
{
    const int*   tokens = (const int*)  d_in[0];
    const float* emb    = (const float*)d_in[1];
    const float* Wx     = (const float*)d_in[2];
    const float* Wh     = (const float*)d_in[3];
    const float* lb     = (const float*)d_in[4];
    const float* W1     = (const float*)d_in[5];
    const float* b1     = (const float*)d_in[6];
    const float* W2     = (const float*)d_in[7];
    const float* b2     = (const float*)d_in[8];
    float* out = (float*)d_out;

    cudaFuncSetAttribute(k2_lstm_head,
                         cudaFuncAttributeMaxDynamicSharedMemorySize, K2_SMEM_TOT);

    dim3 g1(BATCH * SEQ / K1_ROWS, GATES / K1_COLS);   // (4000, 4)
    k1_embed_proj<<<g1, 256>>>(tokens, emb, Wx, lb);
    k2_lstm_head<<<BATCH / 8, K2_THREADS, K2_SMEM_TOT>>>(Wh, W1, b1, W2, b2, out);
}

// round 13
// speedup vs baseline: 2.8037x; 1.8591x over previous
#include <cuda_runtime.h>
#include <cuda_bf16.h>
#include <math.h>

#define BATCH 1024
#define SEQ   250
#define EMB   100
#define UNITS 128
#define GATES 512   // 4*UNITS, gate order i,f,g,o
#define DENSE 32

// Scratch: xz = emb[tokens] @ Wx + b, layout [t][b][512], bf16 (262 MB)
__device__ unsigned short g_xz[(size_t)SEQ * BATCH * GATES];

__device__ __forceinline__ float bf2f(unsigned short v) {
    return __uint_as_float(((unsigned int)v) << 16);
}

// ---- mma.sync bf16 helpers (validated in R12 K1) --------------------------
__device__ __forceinline__ void ldsm_x4(unsigned& r0, unsigned& r1,
                                        unsigned& r2, unsigned& r3, unsigned addr) {
    asm volatile("ldmatrix.sync.aligned.m8n8.x4.shared.b16 {%0,%1,%2,%3}, [%4];"
                 : "=r"(r0), "=r"(r1), "=r"(r2), "=r"(r3) : "r"(addr));
}
__device__ __forceinline__ void ldsm_x2(unsigned& r0, unsigned& r1, unsigned addr) {
    asm volatile("ldmatrix.sync.aligned.m8n8.x2.shared.b16 {%0,%1}, [%2];"
                 : "=r"(r0), "=r"(r1) : "r"(addr));
}
__device__ __forceinline__ void mma16816(float* d,
                                         unsigned a0, unsigned a1, unsigned a2, unsigned a3,
                                         unsigned b0, unsigned b1) {
    asm volatile("mma.sync.aligned.m16n8k16.row.col.f32.bf16.bf16.f32 "
                 "{%0,%1,%2,%3}, {%4,%5,%6,%7}, {%8,%9}, {%0,%1,%2,%3};"
                 : "+f"(d[0]), "+f"(d[1]), "+f"(d[2]), "+f"(d[3])
                 : "r"(a0), "r"(a1), "r"(a2), "r"(a3), "r"(b0), "r"(b1));
}

// ---------------------------------------------------------------------------
// K1 (unchanged from R12): embedding gather + input projection via bf16 mma
// ---------------------------------------------------------------------------
#define K1_ROWS 64
#define K1_COLS 128
#define K1_KPAD 112
#define K1_KSTR 120   // smem row stride in bf16 elems (240 B)

__global__ __launch_bounds__(256) void k1_embed_proj(
    const int* __restrict__ tokens, const float* __restrict__ emb,
    const float* __restrict__ Wx, const float* __restrict__ bias)
{
    __shared__ __align__(16) __nv_bfloat16 As[K1_ROWS][K1_KSTR];  // 15360 B
    __shared__ __align__(16) __nv_bfloat16 Bs[K1_COLS][K1_KSTR];  // 30720 B
    __shared__ int tk[K1_ROWS];

    const int tid  = threadIdx.x;
    const int row0 = blockIdx.x * K1_ROWS;    // global row = b*SEQ + t
    const int c0   = blockIdx.y * K1_COLS;

    if (tid < K1_ROWS) tk[tid] = tokens[row0 + tid];
    __syncthreads();

    {
        const float4* emb4 = (const float4*)emb;
        for (int idx = tid; idx < K1_ROWS * (EMB / 4); idx += 256) {
            int r = idx & 63;
            int q = idx >> 6;                 // float4 index 0..24
            float4 v = emb4[(size_t)tk[r] * (EMB / 4) + q];
            *(__nv_bfloat162*)&As[r][q * 4]     = __floats2bfloat162_rn(v.x, v.y);
            *(__nv_bfloat162*)&As[r][q * 4 + 2] = __floats2bfloat162_rn(v.z, v.w);
        }
        for (int idx = tid; idx < K1_ROWS * 10; idx += 256) {
            int r = idx / 10, j = idx % 10;
            *(__nv_bfloat162*)&As[r][EMB + 2 * j] = __floats2bfloat162_rn(0.f, 0.f);
        }
    }
    {
        for (int idx = tid; idx < EMB * K1_COLS; idx += 256) {
            int e = idx >> 7, n = idx & 127;
            Bs[n][e] = __float2bfloat16(Wx[(size_t)e * GATES + c0 + n]);
        }
        for (int idx = tid; idx < K1_COLS * 10; idx += 256) {
            int n = idx / 10, j = idx % 10;
            *(__nv_bfloat162*)&Bs[n][EMB + 2 * j] = __floats2bfloat162_rn(0.f, 0.f);
        }
    }
    __syncthreads();

    const int wid  = tid >> 5;
    const int lane = tid & 31;
    const int rw   = wid & 3;
    const int cw   = wid >> 2;

    float acc[8][4];
    #pragma unroll
    for (int j = 0; j < 8; j++) {
        float2 bv = *(const float2*)&bias[c0 + cw * 64 + j * 8 + (lane & 3) * 2];
        acc[j][0] = bv.x; acc[j][1] = bv.y;
        acc[j][2] = bv.x; acc[j][3] = bv.y;
    }

    unsigned a_base = (unsigned)__cvta_generic_to_shared(
                          &As[rw * 16 + (lane & 15)][0]) + ((lane >> 4) * 8) * 2;
    unsigned b_base = (unsigned)__cvta_generic_to_shared(
                          &Bs[cw * 64 + (lane & 7)][0]) + (((lane >> 3) & 1) * 8) * 2;

    #pragma unroll
    for (int k = 0; k < K1_KPAD / 16; k++) {
        unsigned a0, a1, a2, a3;
        ldsm_x4(a0, a1, a2, a3, a_base + k * 32);
        #pragma unroll
        for (int j = 0; j < 8; j++) {
            unsigned b0, b1;
            ldsm_x2(b0, b1, b_base + j * (8 * K1_KSTR * 2) + k * 32);
            mma16816(acc[j], a0, a1, a2, a3, b0, b1);
        }
    }

    {
        int r_lo = row0 + rw * 16 + (lane >> 2);
        int r_hi = r_lo + 8;
        int b_lo = r_lo / SEQ, t_lo = r_lo - b_lo * SEQ;
        int b_hi = r_hi / SEQ, t_hi = r_hi - b_hi * SEQ;
        size_t base_lo = ((size_t)t_lo * BATCH + b_lo) * GATES;
        size_t base_hi = ((size_t)t_hi * BATCH + b_hi) * GATES;
        int colb = c0 + cw * 64 + (lane & 3) * 2;
        #pragma unroll
        for (int j = 0; j < 8; j++) {
            int col = colb + j * 8;
            *(__nv_bfloat162*)&g_xz[base_lo + col] =
                __floats2bfloat162_rn(acc[j][0], acc[j][1]);
            *(__nv_bfloat162*)&g_xz[base_hi + col] =
                __floats2bfloat162_rn(acc[j][2], acc[j][3]);
        }
    }
}

// ---------------------------------------------------------------------------
// K2 (v7): tensor-core LSTM recurrence + dense head
//   128 CTAs x 8 batch rows, 512 threads = 16 warps.
//   Per step: z[16 pad rows][512] = h[16][128] @ Wh (bf16 mma, acc init = xz).
//   Warp w owns gate-cols [w*32, w*32+32): 8 k-chunks x 4 n-tiles = 32 mma.
//   ALL of Wh is register-resident as B fragments (64 regs/thread), loaded
//   once via ldsm_x2. h lives in smem hs[16][136] bf16 (rows 8-15 zero);
//   z round-trips through padded zs[4][128][10] fp32 for the gate gather.
//   Gate math: tanh.approx; c-state in regs (thread (u,q) owns rows 2q,2q+1).
// ---------------------------------------------------------------------------
#define K2_THREADS 512
#define HS_STR   136                         // bf16 elems per hs row (272 B)
#define ZS_RSTR  10                          // fp32 per (g,u) cell (rows 0-7 + pad)
#define SM_HS_BYTES   (16 * HS_STR * 2)      // 4352
#define SM_ZS_BYTES   (4 * UNITS * ZS_RSTR * 4)  // 20480
#define SM_D1S_BYTES  (8 * DENSE * 4)        // 1024
#define SM_BST_BYTES  (128 * HS_STR * 2)     // 34816 (staging overlay)
#define SM_TOTAL      (SM_HS_BYTES + SM_BST_BYTES)  // 39168

__device__ __forceinline__ float tanh_fast(float x) {
    float r;
    asm("tanh.approx.f32 %0, %1;" : "=f"(r) : "f"(x));
    return r;
}
__device__ __forceinline__ float sigm_fast(float x) {
    return fmaf(0.5f, tanh_fast(0.5f * x), 0.5f);
}

__global__ __launch_bounds__(K2_THREADS, 1) void k2_lstm_head(
    const float* __restrict__ Wh,
    const float* __restrict__ W1, const float* __restrict__ b1,
    const float* __restrict__ W2, const float* __restrict__ b2,
    float* __restrict__ out)
{
    __shared__ __align__(16) unsigned char sm[SM_TOTAL];
    __nv_bfloat16 (*hs)[HS_STR] = (__nv_bfloat16 (*)[HS_STR])sm;          // [16][136]
    float* zs = (float*)(sm + SM_HS_BYTES);                               // [4][128][10]
    float (*d1s)[DENSE] = (float (*)[DENSE])(sm + SM_HS_BYTES + SM_ZS_BYTES);
    __nv_bfloat16 (*BsT)[HS_STR] = (__nv_bfloat16 (*)[HS_STR])(sm + SM_HS_BYTES); // overlay

    const int tid  = threadIdx.x;
    const int warp = tid >> 5;
    const int lane = tid & 31;
    const int b0   = blockIdx.x * 8;

    // ---- one-time: build register-resident B fragments of Wh ----
    // Phase p stages Wh cols [p*128, p*128+128) as BsT[n][k] bf16; warps
    // 4p..4p+3 extract their (n=32 x k=128) fragments.
    unsigned breg[8][4][2];
    #pragma unroll 1
    for (int p = 0; p < 4; p++) {
        for (int idx = tid; idx < 128 * 128; idx += K2_THREADS) {
            int n = idx & 127, k = idx >> 7;
            BsT[n][k] = __float2bfloat16(Wh[(size_t)k * GATES + p * 128 + n]);
        }
        __syncthreads();
        if ((warp >> 2) == p) {
            unsigned b_base = (unsigned)__cvta_generic_to_shared(
                &BsT[(warp & 3) * 32 + (lane & 7)][0]) + (((lane >> 3) & 1) * 8) * 2;
            #pragma unroll
            for (int kk = 0; kk < 8; kk++)
                #pragma unroll
                for (int j = 0; j < 4; j++)
                    ldsm_x2(breg[kk][j][0], breg[kk][j][1],
                            b_base + j * (8 * HS_STR * 2) + kk * 32);
        }
        __syncthreads();
    }

    // ---- init h = 0 (all 16 rows incl. padding) ----
    for (int i = tid; i < 16 * HS_STR; i += K2_THREADS)
        ((unsigned short*)sm)[i] = 0;
    float c[2] = {0.0f, 0.0f};     // cell state for rows 2q, 2q+1
    __syncthreads();

    const int u  = tid & 127;      // unit (gate-phase)
    const int q  = tid >> 7;       // row-pair (gate-phase)
    const int gw = warp >> 2;      // this warp's gate
    const int cwu = (warp & 3) * 32;         // unit base of warp's cols
    const int frow = lane >> 2;              // fragment row (batch row)
    unsigned a_base = (unsigned)__cvta_generic_to_shared(
        &hs[lane & 15][(lane >> 4) * 8]);

    for (int t = 0; t < SEQ; t++) {
        // accumulators seeded from xz (bf16): d0/d1 = (row frow, cols col, col+1)
        float d[4][4];
        {
            const unsigned short* xzr =
                &g_xz[((size_t)t * BATCH + b0 + frow) * GATES
                      + warp * 32 + (lane & 3) * 2];
            #pragma unroll
            for (int j = 0; j < 4; j++) {
                unsigned v = *(const unsigned*)&xzr[j * 8];
                d[j][0] = bf2f((unsigned short)(v & 0xFFFF));
                d[j][1] = bf2f((unsigned short)(v >> 16));
                d[j][2] = 0.0f; d[j][3] = 0.0f;
            }
        }

        // z += h @ Wh  (A from smem per k-chunk, B register-resident)
        #pragma unroll
        for (int kk = 0; kk < 8; kk++) {
            unsigned a0, a1, a2, a3;
            ldsm_x4(a0, a1, a2, a3, a_base + kk * 32);
            #pragma unroll
            for (int j = 0; j < 4; j++)
                mma16816(d[j], a0, a1, a2, a3, breg[kk][j][0], breg[kk][j][1]);
        }

        // scatter real-row z to zs[g][u][r]
        #pragma unroll
        for (int j = 0; j < 4; j++) {
            int uu = cwu + j * 8 + (lane & 3) * 2;
            zs[(gw * UNITS + uu) * ZS_RSTR + frow]       = d[j][0];
            zs[(gw * UNITS + uu + 1) * ZS_RSTR + frow]   = d[j][1];
        }
        __syncthreads();

        // gate math for rows 2q, 2q+1 of unit u
        float zi[4][2];
        #pragma unroll
        for (int g = 0; g < 4; g++) {
            float2 zp = *(const float2*)&zs[(g * UNITS + u) * ZS_RSTR + 2 * q];
            zi[g][0] = zp.x; zi[g][1] = zp.y;
        }
        #pragma unroll
        for (int h = 0; h < 2; h++) {
            float ig = sigm_fast(zi[0][h]);
            float fg = sigm_fast(zi[1][h]);
            float gg = tanh_fast(zi[2][h]);
            float og = sigm_fast(zi[3][h]);
            float cc = fg * c[h] + ig * gg;
            c[h] = cc;
            hs[2 * q + h][u] = __float2bfloat16(og * tanh_fast(cc));
        }
        __syncthreads();
    }

    // ---- dense head: relu(h @ W1 + b1) @ W2 + b2, softmax ----
    if (tid < 256) {
        int r = tid >> 5;            // 0..7
        int j = tid & 31;            // 0..31
        float a = b1[j];
        #pragma unroll 8
        for (int k = 0; k < UNITS; k++)
            a += bf2f(((const unsigned short*)hs[r])[k]) * W1[k * DENSE + j];
        d1s[r][j] = fmaxf(a, 0.0f);
    }
    __syncthreads();
    if (tid < 8) {
        float l0 = b2[0], l1 = b2[1];
        #pragma unroll
        for (int j = 0; j < DENSE; j++) {
            float d = d1s[tid][j];
            l0 += d * W2[j * 2 + 0];
            l1 += d * W2[j * 2 + 1];
        }
        float m  = fmaxf(l0, l1);
        float e0 = __expf(l0 - m), e1 = __expf(l1 - m);
        float s  = __fdividef(1.0f, e0 + e1);
        out[(b0 + tid) * 2 + 0] = e0 * s;
        out[(b0 + tid) * 2 + 1] = e1 * s;
    }
}

// ---------------------------------------------------------------------------
extern "C" void kernel_launch(void* const* d_in, const int* in_sizes, int n_in,
                              void* d_out, int out_size)
{
    const int*   tokens = (const int*)  d_in[0];
    const float* emb    = (const float*)d_in[1];
    const float* Wx     = (const float*)d_in[2];
    const float* Wh     = (const float*)d_in[3];
    const float* lb     = (const float*)d_in[4];
    const float* W1     = (const float*)d_in[5];
    const float* b1     = (const float*)d_in[6];
    const float* W2     = (const float*)d_in[7];
    const float* b2     = (const float*)d_in[8];
    float* out = (float*)d_out;

    dim3 g1(BATCH * SEQ / K1_ROWS, GATES / K1_COLS);   // (4000, 4)
    k1_embed_proj<<<g1, 256>>>(tokens, emb, Wx, lb);
    k2_lstm_head<<<BATCH / 8, K2_THREADS>>>(Wh, W1, b1, W2, b2, out);
}

// round 14
// speedup vs baseline: 3.6982x; 1.3190x over previous
#include <cuda_runtime.h>
#include <cuda_bf16.h>
#include <math.h>

#define BATCH 1024
#define SEQ   250
#define EMB   100
#define UNITS 128
#define GATES 512   // 4*UNITS, gate order i,f,g,o
#define DENSE 32

// Scratch: xz = emb[tokens] @ Wx + b, layout [t][b][512], bf16 (262 MB)
__device__ unsigned short g_xz[(size_t)SEQ * BATCH * GATES];

__device__ __forceinline__ float bf2f(unsigned short v) {
    return __uint_as_float(((unsigned int)v) << 16);
}

// ---- mma.sync bf16 helpers (validated R12/R13) -----------------------------
__device__ __forceinline__ void ldsm_x4(unsigned& r0, unsigned& r1,
                                        unsigned& r2, unsigned& r3, unsigned addr) {
    asm volatile("ldmatrix.sync.aligned.m8n8.x4.shared.b16 {%0,%1,%2,%3}, [%4];"
                 : "=r"(r0), "=r"(r1), "=r"(r2), "=r"(r3) : "r"(addr));
}
__device__ __forceinline__ void ldsm_x2(unsigned& r0, unsigned& r1, unsigned addr) {
    asm volatile("ldmatrix.sync.aligned.m8n8.x2.shared.b16 {%0,%1}, [%2];"
                 : "=r"(r0), "=r"(r1) : "r"(addr));
}
__device__ __forceinline__ void mma16816(float* d,
                                         unsigned a0, unsigned a1, unsigned a2, unsigned a3,
                                         unsigned b0, unsigned b1) {
    asm volatile("mma.sync.aligned.m16n8k16.row.col.f32.bf16.bf16.f32 "
                 "{%0,%1,%2,%3}, {%4,%5,%6,%7}, {%8,%9}, {%0,%1,%2,%3};"
                 : "+f"(d[0]), "+f"(d[1]), "+f"(d[2]), "+f"(d[3])
                 : "r"(a0), "r"(a1), "r"(a2), "r"(a3), "r"(b0), "r"(b1));
}

// ---------------------------------------------------------------------------
// K1 (v4): embedding gather + input projection via bf16 mma
//   Tile 64 rows x 256 cols (grid 4000 x 2): halves B-staging + A-gather
//   duplication vs v3. Dynamic smem 76.8KB -> 2 CTAs/SM.
//   Epilogue stages fragments into smem zb[64][264] bf16 (conflict-free),
//   then stores coalesced 512B/row chunks (STG.128) instead of scattered
//   4B stores.
// ---------------------------------------------------------------------------
#define K1_ROWS  64
#define K1_COLSB 256
#define K1_KPAD  112
#define K1_KSTR  120   // smem row stride in bf16 elems (240 B)
#define K1_AS_BYTES (K1_ROWS * K1_KSTR * 2)            // 15360
#define K1_BS_BYTES (K1_COLSB * K1_KSTR * 2)           // 61440
#define K1_SMEM     (K1_AS_BYTES + K1_BS_BYTES)        // 76800
#define ZB_STR   264   // bf16 elems per zb row (528 B; 132 words % 32 = 4)

__global__ __launch_bounds__(256) void k1_embed_proj(
    const int* __restrict__ tokens, const float* __restrict__ emb,
    const float* __restrict__ Wx, const float* __restrict__ bias)
{
    extern __shared__ __align__(16) unsigned char k1sm[];
    __nv_bfloat16 (*As)[K1_KSTR] = (__nv_bfloat16 (*)[K1_KSTR])k1sm;
    __nv_bfloat16 (*Bs)[K1_KSTR] = (__nv_bfloat16 (*)[K1_KSTR])(k1sm + K1_AS_BYTES);
    __nv_bfloat16 (*zb)[ZB_STR]  = (__nv_bfloat16 (*)[ZB_STR])(k1sm + K1_AS_BYTES);
    __shared__ int tk[K1_ROWS];

    const int tid  = threadIdx.x;
    const int row0 = blockIdx.x * K1_ROWS;    // global row = b*SEQ + t
    const int c0   = blockIdx.y * K1_COLSB;

    if (tid < K1_ROWS) tk[tid] = tokens[row0 + tid];
    __syncthreads();

    // ---- stage A: gathered emb rows -> bf16 [r][k] ----
    {
        const float4* emb4 = (const float4*)emb;
        for (int idx = tid; idx < K1_ROWS * (EMB / 4); idx += 256) {
            int r = idx & 63;
            int q = idx >> 6;                 // float4 index 0..24
            float4 v = emb4[(size_t)tk[r] * (EMB / 4) + q];
            *(__nv_bfloat162*)&As[r][q * 4]     = __floats2bfloat162_rn(v.x, v.y);
            *(__nv_bfloat162*)&As[r][q * 4 + 2] = __floats2bfloat162_rn(v.z, v.w);
        }
        for (int idx = tid; idx < K1_ROWS * 10; idx += 256) {
            int r = idx / 10, j = idx % 10;
            *(__nv_bfloat162*)&As[r][EMB + 2 * j] = __floats2bfloat162_rn(0.f, 0.f);
        }
    }
    // ---- stage B: Wx transposed -> Bs[n][k] bf16 (256 cols) ----
    {
        for (int idx = tid; idx < EMB * K1_COLSB; idx += 256) {
            int e = idx >> 8, n = idx & 255;
            Bs[n][e] = __float2bfloat16(Wx[(size_t)e * GATES + c0 + n]);
        }
        for (int idx = tid; idx < K1_COLSB * 10; idx += 256) {
            int n = idx / 10, j = idx % 10;
            *(__nv_bfloat162*)&Bs[n][EMB + 2 * j] = __floats2bfloat162_rn(0.f, 0.f);
        }
    }
    __syncthreads();

    const int wid  = tid >> 5;
    const int lane = tid & 31;
    const int rw   = wid & 3;     // row-warp: rows rw*16..+15
    const int cw   = wid >> 2;    // col-warp: cols cw*128..+127
    const int frow = lane >> 2;

    // 16 n8-tiles per warp, bias-initialized accumulators
    float acc[16][4];
    #pragma unroll
    for (int j = 0; j < 16; j++) {
        float2 bv = *(const float2*)&bias[c0 + cw * 128 + j * 8 + (lane & 3) * 2];
        acc[j][0] = bv.x; acc[j][1] = bv.y;
        acc[j][2] = bv.x; acc[j][3] = bv.y;
    }

    unsigned a_base = (unsigned)__cvta_generic_to_shared(
                          &As[rw * 16 + (lane & 15)][0]) + ((lane >> 4) * 8) * 2;
    unsigned b_base = (unsigned)__cvta_generic_to_shared(
                          &Bs[cw * 128 + (lane & 7)][0]) + (((lane >> 3) & 1) * 8) * 2;

    #pragma unroll
    for (int k = 0; k < K1_KPAD / 16; k++) {
        unsigned a0, a1, a2, a3;
        ldsm_x4(a0, a1, a2, a3, a_base + k * 32);
        #pragma unroll
        for (int j = 0; j < 16; j++) {
            unsigned b0, b1;
            ldsm_x2(b0, b1, b_base + j * (8 * K1_KSTR * 2) + k * 32);
            mma16816(acc[j], a0, a1, a2, a3, b0, b1);
        }
    }
    __syncthreads();   // mma reads done; zb may overlay Bs now

    // ---- fragments -> zb (bank-conflict-free: bank == lane per j) ----
    {
        int r_lo = rw * 16 + frow;
        int colb = cw * 128 + (lane & 3) * 2;
        #pragma unroll
        for (int j = 0; j < 16; j++) {
            int col = colb + j * 8;
            *(__nv_bfloat162*)&zb[r_lo][col] =
                __floats2bfloat162_rn(acc[j][0], acc[j][1]);
            *(__nv_bfloat162*)&zb[r_lo + 8][col] =
                __floats2bfloat162_rn(acc[j][2], acc[j][3]);
        }
    }
    __syncthreads();

    // ---- coalesced store: 512B per row (32 x 16B chunks) ----
    for (int idx = tid; idx < K1_ROWS * 32; idx += 256) {
        int row = idx >> 5, ch = idx & 31;
        int gr = row0 + row;
        int b  = gr / SEQ;
        int t  = gr - b * SEQ;
        size_t off = ((size_t)t * BATCH + b) * GATES + c0 + ch * 8;
        uint4 v = *(uint4*)&zb[row][ch * 8];
        __stcs((uint4*)&g_xz[off], v);
    }
}

// ---------------------------------------------------------------------------
// K2 (v8): tensor-core LSTM recurrence + dense head
//   Same as R13 winner, plus: xz seed is SOFTWARE-PIPELINED — registers for
//   step t+1 loaded (__ldcs) right after step t's accumulators are seeded,
//   hiding the DRAM latency behind 32 mma + 2 barriers + gate math.
// ---------------------------------------------------------------------------
#define K2_THREADS 512
#define HS_STR   136
#define ZS_RSTR  10
#define SM_HS_BYTES   (16 * HS_STR * 2)
#define SM_ZS_BYTES   (4 * UNITS * ZS_RSTR * 4)
#define SM_BST_BYTES  (128 * HS_STR * 2)
#define SM_TOTAL      (SM_HS_BYTES + SM_BST_BYTES)

__device__ __forceinline__ float tanh_fast(float x) {
    float r;
    asm("tanh.approx.f32 %0, %1;" : "=f"(r) : "f"(x));
    return r;
}
__device__ __forceinline__ float sigm_fast(float x) {
    return fmaf(0.5f, tanh_fast(0.5f * x), 0.5f);
}

__global__ __launch_bounds__(K2_THREADS, 1) void k2_lstm_head(
    const float* __restrict__ Wh,
    const float* __restrict__ W1, const float* __restrict__ b1,
    const float* __restrict__ W2, const float* __restrict__ b2,
    float* __restrict__ out)
{
    __shared__ __align__(16) unsigned char sm[SM_TOTAL];
    __nv_bfloat16 (*hs)[HS_STR] = (__nv_bfloat16 (*)[HS_STR])sm;
    float* zs = (float*)(sm + SM_HS_BYTES);
    float (*d1s)[DENSE] = (float (*)[DENSE])(sm + SM_HS_BYTES + SM_ZS_BYTES);
    __nv_bfloat16 (*BsT)[HS_STR] = (__nv_bfloat16 (*)[HS_STR])(sm + SM_HS_BYTES);

    const int tid  = threadIdx.x;
    const int warp = tid >> 5;
    const int lane = tid & 31;
    const int b0   = blockIdx.x * 8;

    // ---- one-time: register-resident B fragments of Wh ----
    unsigned breg[8][4][2];
    #pragma unroll 1
    for (int p = 0; p < 4; p++) {
        for (int idx = tid; idx < 128 * 128; idx += K2_THREADS) {
            int n = idx & 127, k = idx >> 7;
            BsT[n][k] = __float2bfloat16(Wh[(size_t)k * GATES + p * 128 + n]);
        }
        __syncthreads();
        if ((warp >> 2) == p) {
            unsigned b_base = (unsigned)__cvta_generic_to_shared(
                &BsT[(warp & 3) * 32 + (lane & 7)][0]) + (((lane >> 3) & 1) * 8) * 2;
            #pragma unroll
            for (int kk = 0; kk < 8; kk++)
                #pragma unroll
                for (int j = 0; j < 4; j++)
                    ldsm_x2(breg[kk][j][0], breg[kk][j][1],
                            b_base + j * (8 * HS_STR * 2) + kk * 32);
        }
        __syncthreads();
    }

    // ---- init h = 0 ----
    for (int i = tid; i < 16 * HS_STR; i += K2_THREADS)
        ((unsigned short*)sm)[i] = 0;
    float c[2] = {0.0f, 0.0f};
    __syncthreads();

    const int u  = tid & 127;
    const int q  = tid >> 7;
    const int gw = warp >> 2;
    const int cwu = (warp & 3) * 32;
    const int frow = lane >> 2;
    unsigned a_base = (unsigned)__cvta_generic_to_shared(
        &hs[lane & 15][(lane >> 4) * 8]);

    // pipelined xz: pointer + current regs
    const unsigned short* xzp =
        &g_xz[((size_t)b0 + frow) * GATES + warp * 32 + (lane & 3) * 2];
    unsigned xcur[4];
    #pragma unroll
    for (int j = 0; j < 4; j++)
        xcur[j] = __ldcs((const unsigned*)&xzp[j * 8]);

    for (int t = 0; t < SEQ; t++) {
        // seed accumulators from prefetched xz
        float d[4][4];
        #pragma unroll
        for (int j = 0; j < 4; j++) {
            d[j][0] = bf2f((unsigned short)(xcur[j] & 0xFFFF));
            d[j][1] = bf2f((unsigned short)(xcur[j] >> 16));
            d[j][2] = 0.0f; d[j][3] = 0.0f;
        }
        // issue next step's loads (hidden behind mma + barriers + gates)
        if (t + 1 < SEQ) {
            xzp += (size_t)BATCH * GATES;
            #pragma unroll
            for (int j = 0; j < 4; j++)
                xcur[j] = __ldcs((const unsigned*)&xzp[j * 8]);
        }

        // z += h @ Wh
        #pragma unroll
        for (int kk = 0; kk < 8; kk++) {
            unsigned a0, a1, a2, a3;
            ldsm_x4(a0, a1, a2, a3, a_base + kk * 32);
            #pragma unroll
            for (int j = 0; j < 4; j++)
                mma16816(d[j], a0, a1, a2, a3, breg[kk][j][0], breg[kk][j][1]);
        }

        // scatter real-row z to zs[g][u][r]
        #pragma unroll
        for (int j = 0; j < 4; j++) {
            int uu = cwu + j * 8 + (lane & 3) * 2;
            zs[(gw * UNITS + uu) * ZS_RSTR + frow]     = d[j][0];
            zs[(gw * UNITS + uu + 1) * ZS_RSTR + frow] = d[j][1];
        }
        __syncthreads();

        // gate math for rows 2q, 2q+1 of unit u
        float zi[4][2];
        #pragma unroll
        for (int g = 0; g < 4; g++) {
            float2 zp = *(const float2*)&zs[(g * UNITS + u) * ZS_RSTR + 2 * q];
            zi[g][0] = zp.x; zi[g][1] = zp.y;
        }
        #pragma unroll
        for (int h = 0; h < 2; h++) {
            float ig = sigm_fast(zi[0][h]);
            float fg = sigm_fast(zi[1][h]);
            float gg = tanh_fast(zi[2][h]);
            float og = sigm_fast(zi[3][h]);
            float cc = fg * c[h] + ig * gg;
            c[h] = cc;
            hs[2 * q + h][u] = __float2bfloat16(og * tanh_fast(cc));
        }
        __syncthreads();
    }

    // ---- dense head: relu(h @ W1 + b1) @ W2 + b2, softmax ----
    if (tid < 256) {
        int r = tid >> 5;
        int j = tid & 31;
        float a = b1[j];
        #pragma unroll 8
        for (int k = 0; k < UNITS; k++)
            a += bf2f(((const unsigned short*)hs[r])[k]) * W1[k * DENSE + j];
        d1s[r][j] = fmaxf(a, 0.0f);
    }
    __syncthreads();
    if (tid < 8) {
        float l0 = b2[0], l1 = b2[1];
        #pragma unroll
        for (int j = 0; j < DENSE; j++) {
            float d = d1s[tid][j];
            l0 += d * W2[j * 2 + 0];
            l1 += d * W2[j * 2 + 1];
        }
        float m  = fmaxf(l0, l1);
        float e0 = __expf(l0 - m), e1 = __expf(l1 - m);
        float s  = __fdividef(1.0f, e0 + e1);
        out[(b0 + tid) * 2 + 0] = e0 * s;
        out[(b0 + tid) * 2 + 1] = e1 * s;
    }
}

// ---------------------------------------------------------------------------
extern "C" void kernel_launch(void* const* d_in, const int* in_sizes, int n_in,
                              void* d_out, int out_size)
{
    const int*   tokens = (const int*)  d_in[0];
    const float* emb    = (const float*)d_in[1];
    const float* Wx     = (const float*)d_in[2];
    const float* Wh     = (const float*)d_in[3];
    const float* lb     = (const float*)d_in[4];
    const float* W1     = (const float*)d_in[5];
    const float* b1     = (const float*)d_in[6];
    const float* W2     = (const float*)d_in[7];
    const float* b2     = (const float*)d_in[8];
    float* out = (float*)d_out;

    cudaFuncSetAttribute(k1_embed_proj,
                         cudaFuncAttributeMaxDynamicSharedMemorySize, K1_SMEM);

    dim3 g1(BATCH * SEQ / K1_ROWS, GATES / K1_COLSB);   // (4000, 2)
    k1_embed_proj<<<g1, 256, K1_SMEM>>>(tokens, emb, Wx, lb);
    k2_lstm_head<<<BATCH / 8, K2_THREADS>>>(Wh, W1, b1, W2, b2, out);
}

// round 15
// speedup vs baseline: 4.4312x; 1.1982x over previous
#include <cuda_runtime.h>
#include <cuda_bf16.h>
#include <math.h>

#define BATCH 1024
#define SEQ   250
#define EMB   100
#define VOCAB 50001
#define UNITS 128
#define GATES 512   // 4*UNITS, gate order i,f,g,o
#define DENSE 32

// Scratch: xz = emb[tokens] @ Wx + b, layout [t][b][512], bf16 (262 MB)
__device__ unsigned short g_xz[(size_t)SEQ * BATCH * GATES];
// Pre-converted operands (one-time kernels)
__device__ unsigned short g_WxT[GATES * 120];          // [n][k] bf16, k padded 120
__device__ unsigned short g_embh[(size_t)VOCAB * EMB]; // bf16 emb

__device__ __forceinline__ float bf2f(unsigned short v) {
    return __uint_as_float(((unsigned int)v) << 16);
}

// ---- mma.sync bf16 helpers (validated R12-R14) -----------------------------
__device__ __forceinline__ void ldsm_x4(unsigned& r0, unsigned& r1,
                                        unsigned& r2, unsigned& r3, unsigned addr) {
    asm volatile("ldmatrix.sync.aligned.m8n8.x4.shared.b16 {%0,%1,%2,%3}, [%4];"
                 : "=r"(r0), "=r"(r1), "=r"(r2), "=r"(r3) : "r"(addr));
}
__device__ __forceinline__ void ldsm_x2(unsigned& r0, unsigned& r1, unsigned addr) {
    asm volatile("ldmatrix.sync.aligned.m8n8.x2.shared.b16 {%0,%1}, [%2];"
                 : "=r"(r0), "=r"(r1) : "r"(addr));
}
__device__ __forceinline__ void mma16816(float* d,
                                         unsigned a0, unsigned a1, unsigned a2, unsigned a3,
                                         unsigned b0, unsigned b1) {
    asm volatile("mma.sync.aligned.m16n8k16.row.col.f32.bf16.bf16.f32 "
                 "{%0,%1,%2,%3}, {%4,%5,%6,%7}, {%8,%9}, {%0,%1,%2,%3};"
                 : "+f"(d[0]), "+f"(d[1]), "+f"(d[2]), "+f"(d[3])
                 : "r"(a0), "r"(a1), "r"(a2), "r"(a3), "r"(b0), "r"(b1));
}

// ---------------------------------------------------------------------------
// K0a: Wx -> bf16 transposed [n][k], k padded to 120 with zeros
// ---------------------------------------------------------------------------
__global__ void k0_wx(const float* __restrict__ Wx)
{
    int n = blockIdx.x;
    for (int k = threadIdx.x; k < 120; k += 128)
        g_WxT[n * 120 + k] = (k < EMB)
            ? (unsigned short)__bfloat16_as_ushort(__float2bfloat16(Wx[(size_t)k * GATES + n]))
            : (unsigned short)0;
}
// K0b: emb -> bf16
__global__ void k0_emb(const float* __restrict__ emb)
{
    for (size_t i = blockIdx.x * blockDim.x + threadIdx.x;
         i < (size_t)VOCAB * EMB; i += (size_t)gridDim.x * blockDim.x)
        g_embh[i] = (unsigned short)__bfloat16_as_ushort(__float2bfloat16(emb[i]));
}

// ---------------------------------------------------------------------------
// K1 (v5): embedding gather + input projection via bf16 mma
//   Tile 64 rows x 256 cols (grid 4000 x 2), staging from PRE-CONVERTED bf16:
//   B-stage = uint4 memcpy of WxT rows (15 uint4/thread vs 100 LDG+CVT+STS),
//   A-gather = uint2 copies of bf16 emb rows. Epilogue: fragments -> smem zb
//   -> coalesced 16B stores (R14 path).
// ---------------------------------------------------------------------------
#define K1_ROWS  64
#define K1_COLSB 256
#define K1_KPAD  112
#define K1_KSTR  120   // smem row stride in bf16 elems (240 B)
#define K1_AS_BYTES (K1_ROWS * K1_KSTR * 2)            // 15360
#define K1_BS_BYTES (K1_COLSB * K1_KSTR * 2)           // 61440
#define K1_SMEM     (K1_AS_BYTES + K1_BS_BYTES)        // 76800
#define ZB_STR   264   // bf16 elems per zb row (528 B)

__global__ __launch_bounds__(256) void k1_embed_proj(
    const int* __restrict__ tokens, const float* __restrict__ bias)
{
    extern __shared__ __align__(16) unsigned char k1sm[];
    unsigned short (*As)[K1_KSTR] = (unsigned short (*)[K1_KSTR])k1sm;
    unsigned short (*Bs)[K1_KSTR] = (unsigned short (*)[K1_KSTR])(k1sm + K1_AS_BYTES);
    __nv_bfloat16 (*zb)[ZB_STR]   = (__nv_bfloat16 (*)[ZB_STR])(k1sm + K1_AS_BYTES);
    __shared__ int tk[K1_ROWS];

    const int tid  = threadIdx.x;
    const int row0 = blockIdx.x * K1_ROWS;    // global row = b*SEQ + t
    const int c0   = blockIdx.y * K1_COLSB;

    if (tid < K1_ROWS) tk[tid] = tokens[row0 + tid];
    __syncthreads();

    // ---- stage A: gathered bf16 emb rows (25 uint2 per row) ----
    for (int idx = tid; idx < K1_ROWS * 25; idx += 256) {
        int r = idx / 25, q = idx - r * 25;
        *(uint2*)&As[r][q * 4] =
            *(const uint2*)&g_embh[(size_t)tk[r] * EMB + q * 4];
    }
    // zero K tail 100..119
    for (int idx = tid; idx < K1_ROWS * 5; idx += 256) {
        int r = idx / 5, j = idx - r * 5;
        *(uint2*)&As[r][EMB + 4 * j] = make_uint2(0u, 0u);
    }
    // ---- stage B: memcpy pre-transposed WxT rows (15 uint4 per row) ----
    for (int idx = tid; idx < K1_COLSB * 15; idx += 256) {
        int n = idx / 15, q = idx - n * 15;
        *(uint4*)&Bs[n][q * 8] =
            *(const uint4*)&g_WxT[(size_t)(c0 + n) * K1_KSTR + q * 8];
    }
    __syncthreads();

    const int wid  = tid >> 5;
    const int lane = tid & 31;
    const int rw   = wid & 3;     // row-warp: rows rw*16..+15
    const int cw   = wid >> 2;    // col-warp: cols cw*128..+127
    const int frow = lane >> 2;

    float acc[16][4];
    #pragma unroll
    for (int j = 0; j < 16; j++) {
        float2 bv = *(const float2*)&bias[c0 + cw * 128 + j * 8 + (lane & 3) * 2];
        acc[j][0] = bv.x; acc[j][1] = bv.y;
        acc[j][2] = bv.x; acc[j][3] = bv.y;
    }

    unsigned a_base = (unsigned)__cvta_generic_to_shared(
                          &As[rw * 16 + (lane & 15)][0]) + ((lane >> 4) * 8) * 2;
    unsigned b_base = (unsigned)__cvta_generic_to_shared(
                          &Bs[cw * 128 + (lane & 7)][0]) + (((lane >> 3) & 1) * 8) * 2;

    #pragma unroll
    for (int k = 0; k < K1_KPAD / 16; k++) {
        unsigned a0, a1, a2, a3;
        ldsm_x4(a0, a1, a2, a3, a_base + k * 32);
        #pragma unroll
        for (int j = 0; j < 16; j++) {
            unsigned b0, b1;
            ldsm_x2(b0, b1, b_base + j * (8 * K1_KSTR * 2) + k * 32);
            mma16816(acc[j], a0, a1, a2, a3, b0, b1);
        }
    }
    __syncthreads();   // mma reads done; zb overlays Bs

    // ---- fragments -> zb ----
    {
        int r_lo = rw * 16 + frow;
        int colb = cw * 128 + (lane & 3) * 2;
        #pragma unroll
        for (int j = 0; j < 16; j++) {
            int col = colb + j * 8;
            *(__nv_bfloat162*)&zb[r_lo][col] =
                __floats2bfloat162_rn(acc[j][0], acc[j][1]);
            *(__nv_bfloat162*)&zb[r_lo + 8][col] =
                __floats2bfloat162_rn(acc[j][2], acc[j][3]);
        }
    }
    __syncthreads();

    // ---- coalesced store: 512B per row ----
    for (int idx = tid; idx < K1_ROWS * 32; idx += 256) {
        int row = idx >> 5, ch = idx & 31;
        int gr = row0 + row;
        int b  = gr / SEQ;
        int t  = gr - b * SEQ;
        size_t off = ((size_t)t * BATCH + b) * GATES + c0 + ch * 8;
        uint4 v = *(uint4*)&zb[row][ch * 8];
        __stcs((uint4*)&g_xz[off], v);
    }
}

// ---------------------------------------------------------------------------
// K2 (v9): tensor-core LSTM recurrence, GATE-ALIGNED columns
//   128 CTAs x 8 batch rows, 512 threads = 16 warps.
//   Warp w owns n8-tile j at cols j*128 + w*8 (one tile PER GATE, units
//   w*8..w*8+7). Fragment slot d[j][h] = gate j of cell (row frow, unit
//   w*8+(lane&3)*2+h) -> gate math is pure register math. No z buffer,
//   no scatter/gather, ONE barrier per step (hs double-buffered).
// ---------------------------------------------------------------------------
#define K2_THREADS 512
#define HS_STR   136
#define HSBUF_BYTES (16 * HS_STR * 2)                  // 4352 per buffer
#define SM_HS_BYTES (2 * HSBUF_BYTES)                  // 8704
#define SM_BST_BYTES (128 * HS_STR * 2)                // 34816 (setup overlay)
#define SM_TOTAL (SM_HS_BYTES + SM_BST_BYTES)          // 43520

__device__ __forceinline__ float tanh_fast(float x) {
    float r;
    asm("tanh.approx.f32 %0, %1;" : "=f"(r) : "f"(x));
    return r;
}
__device__ __forceinline__ float sigm_fast(float x) {
    return fmaf(0.5f, tanh_fast(0.5f * x), 0.5f);
}

__global__ __launch_bounds__(K2_THREADS, 1) void k2_lstm_head(
    const float* __restrict__ Wh,
    const float* __restrict__ W1, const float* __restrict__ b1,
    const float* __restrict__ W2, const float* __restrict__ b2,
    float* __restrict__ out)
{
    __shared__ __align__(16) unsigned char sm[SM_TOTAL];
    unsigned short (*hs0)[HS_STR] = (unsigned short (*)[HS_STR])sm;  // 2 buffers
    unsigned short (*BsT)[HS_STR] =
        (unsigned short (*)[HS_STR])(sm + SM_HS_BYTES);              // setup overlay
    float (*d1s)[DENSE] = (float (*)[DENSE])(sm + SM_HS_BYTES);      // post-loop overlay

    const int tid  = threadIdx.x;
    const int warp = tid >> 5;
    const int lane = tid & 31;
    const int b0   = blockIdx.x * 8;
    const int frow = lane >> 2;

    // ---- one-time: register-resident B fragments of Wh, gate-aligned ----
    // Phase p stages Wh cols [p*128, p*128+128) as BsT[n][k]; EVERY warp
    // extracts its gate-p fragment from local n = warp*8.
    unsigned breg[8][4][2];
    #pragma unroll 1
    for (int p = 0; p < 4; p++) {
        for (int idx = tid; idx < 128 * 128; idx += K2_THREADS) {
            int n = idx & 127, k = idx >> 7;
            BsT[n][k] = (unsigned short)__bfloat16_as_ushort(
                __float2bfloat16(Wh[(size_t)k * GATES + p * 128 + n]));
        }
        __syncthreads();
        {
            unsigned b_base = (unsigned)__cvta_generic_to_shared(
                &BsT[warp * 8 + (lane & 7)][0]) + (((lane >> 3) & 1) * 8) * 2;
            #pragma unroll
            for (int kk = 0; kk < 8; kk++)
                ldsm_x2(breg[kk][p][0], breg[kk][p][1], b_base + kk * 32);
        }
        __syncthreads();
    }

    // ---- init h buffers = 0 ----
    for (int i = tid; i < 2 * 16 * HS_STR; i += K2_THREADS)
        ((unsigned short*)sm)[i] = 0;
    float c[2] = {0.0f, 0.0f};     // cell state for this thread's 2 units
    __syncthreads();

    unsigned a_base0 = (unsigned)__cvta_generic_to_shared(
        &hs0[lane & 15][(lane >> 4) * 8]);

    // pipelined xz: this thread's 4 gate values x 2 units
    const unsigned short* xzp =
        &g_xz[((size_t)b0 + frow) * GATES + warp * 8 + (lane & 3) * 2];
    unsigned xcur[4];
    #pragma unroll
    for (int j = 0; j < 4; j++)
        xcur[j] = __ldcs((const unsigned*)&xzp[j * UNITS]);

    int cur = 0;
    const int u0 = warp * 8 + (lane & 3) * 2;
    for (int t = 0; t < SEQ; t++) {
        // seed accumulators from prefetched xz
        float d[4][4];
        #pragma unroll
        for (int j = 0; j < 4; j++) {
            d[j][0] = bf2f((unsigned short)(xcur[j] & 0xFFFF));
            d[j][1] = bf2f((unsigned short)(xcur[j] >> 16));
            d[j][2] = 0.0f; d[j][3] = 0.0f;
        }
        if (t + 1 < SEQ) {
            xzp += (size_t)BATCH * GATES;
            #pragma unroll
            for (int j = 0; j < 4; j++)
                xcur[j] = __ldcs((const unsigned*)&xzp[j * UNITS]);
        }

        // z += h @ Wh  (A from hs[cur], B register-resident)
        unsigned a_base = a_base0 + cur * HSBUF_BYTES;
        #pragma unroll
        for (int kk = 0; kk < 8; kk++) {
            unsigned a0, a1, a2, a3;
            ldsm_x4(a0, a1, a2, a3, a_base + kk * 32);
            #pragma unroll
            for (int j = 0; j < 4; j++)
                mma16816(d[j], a0, a1, a2, a3, breg[kk][j][0], breg[kk][j][1]);
        }

        // gate math in registers: d[0..3][h] = i,f,g,o of (frow, u0+h)
        float hv[2];
        #pragma unroll
        for (int h = 0; h < 2; h++) {
            float ig = sigm_fast(d[0][h]);
            float fg = sigm_fast(d[1][h]);
            float gg = tanh_fast(d[2][h]);
            float og = sigm_fast(d[3][h]);
            float cc = fg * c[h] + ig * gg;
            c[h] = cc;
            hv[h] = og * tanh_fast(cc);
        }
        // write h to the other buffer (rows 8-15 stay zero)
        *(__nv_bfloat162*)&hs0[(cur ^ 1) * 16 + frow][u0] =
            __floats2bfloat162_rn(hv[0], hv[1]);
        __syncthreads();
        cur ^= 1;
    }

    // ---- dense head: relu(h @ W1 + b1) @ W2 + b2, softmax ----
    const unsigned short (*hf)[HS_STR] = &hs0[cur * 16];
    if (tid < 256) {
        int r = tid >> 5;
        int j = tid & 31;
        float a = b1[j];
        #pragma unroll 8
        for (int k = 0; k < UNITS; k++)
            a += bf2f(hf[r][k]) * W1[k * DENSE + j];
        d1s[r][j] = fmaxf(a, 0.0f);
    }
    __syncthreads();
    if (tid < 8) {
        float l0 = b2[0], l1 = b2[1];
        #pragma unroll
        for (int j = 0; j < DENSE; j++) {
            float d = d1s[tid][j];
            l0 += d * W2[j * 2 + 0];
            l1 += d * W2[j * 2 + 1];
        }
        float m  = fmaxf(l0, l1);
        float e0 = __expf(l0 - m), e1 = __expf(l1 - m);
        float s  = __fdividef(1.0f, e0 + e1);
        out[(b0 + tid) * 2 + 0] = e0 * s;
        out[(b0 + tid) * 2 + 1] = e1 * s;
    }
}

// ---------------------------------------------------------------------------
extern "C" void kernel_launch(void* const* d_in, const int* in_sizes, int n_in,
                              void* d_out, int out_size)
{
    const int*   tokens = (const int*)  d_in[0];
    const float* emb    = (const float*)d_in[1];
    const float* Wx     = (const float*)d_in[2];
    const float* Wh     = (const float*)d_in[3];
    const float* lb     = (const float*)d_in[4];
    const float* W1     = (const float*)d_in[5];
    const float* b1     = (const float*)d_in[6];
    const float* W2     = (const float*)d_in[7];
    const float* b2     = (const float*)d_in[8];
    float* out = (float*)d_out;

    cudaFuncSetAttribute(k1_embed_proj,
                         cudaFuncAttributeMaxDynamicSharedMemorySize, K1_SMEM);

    k0_wx<<<GATES, 128>>>(Wx);
    k0_emb<<<2048, 256>>>(emb);
    dim3 g1(BATCH * SEQ / K1_ROWS, GATES / K1_COLSB);   // (4000, 2)
    k1_embed_proj<<<g1, 256, K1_SMEM>>>(tokens, lb);
    k2_lstm_head<<<BATCH / 8, K2_THREADS>>>(Wh, W1, b1, W2, b2, out);
}